// round 11
// baseline (speedup 1.0000x reference)
#include <cuda_runtime.h>
#include <cuda_bf16.h>
#include <cuda_fp16.h>
#include <stdint.h>
#include <math.h>

#define NN   4096
#define NG   64
#define NSP  10
#define EPSF 1e-5f
#define INV_H  0.08838834764831845f
#define INV_U  0.125f
#define INV_TP 0.0078125f
#define INV_SC 0.02795084971874737f
#define ISQRT3 0.57735026918962576f

// ---- static scratch ----
static __device__ float g_hp0[NN * 128];
static __device__ float g_hp1[NN * 384];
static __device__ float g_up0[NN * 64];
static __device__ float g_up1[NN * 192];
static __device__ unsigned short g_Ah[(size_t)NN * 16384];   // A pre-split bf16 hi
static __device__ unsigned short g_Al[(size_t)NN * 16384];   // A pre-split bf16 lo
static __device__ unsigned short g_B0h[16384 * 256], g_B0l[16384 * 256];
static __device__ unsigned short g_TAh[128 * 8192],  g_TAl[128 * 8192];
static __device__ unsigned short g_TBh[64 * 16384],  g_TBl[64 * 16384];
static __device__ float g_z0p[(size_t)4 * NN * 256];
static __device__ float g_s[NN * 128];
static __device__ float g_g[NN * 128];
static __device__ unsigned short g_ta[(size_t)NN * 8192];    // fp16
static __device__ unsigned short g_tb[(size_t)NN * 16384];   // fp16
static __device__ float g_vmat[NN * 384];
static __device__ float g_y0[NN * 128];
static __device__ float g_y1[NN * 384];
static __device__ int   g_spi[NN];
static __device__ float g_mean0[NG], g_rs0[NG], g_rs1[NG];

__device__ __forceinline__ void splitbf(float w, unsigned short* h, unsigned short* l)
{
    unsigned hi = (__float_as_uint(w) + 0x8000u) & 0xFFFF0000u;
    *h = (unsigned short)(hi >> 16);
    *l = __bfloat16_as_ushort(__float2bfloat16_rn(w - __uint_as_float(hi)));
}

// ---- prep: split B matrices to bf16 hi/lo ----
__global__ void k_prep(const float* __restrict__ Wt00, const float* __restrict__ Wt11,
                       const float* __restrict__ Wt01, const float* __restrict__ Wt10)
{
    const int S0 = 16384 * 256, S1 = S0 + 128 * 8192, S2 = S1 + 64 * 16384;
    int idx = blockIdx.x * blockDim.x + threadIdx.x;
    if (idx < S0) {
        int k = idx >> 8;
        float w = (k < 8192) ? Wt00[idx] : Wt11[idx - 2097152] * ISQRT3;
        splitbf(w, &g_B0h[idx], &g_B0l[idx]);
    } else if (idx < S1) {
        int j = idx - S0;
        splitbf(Wt01[j], &g_TAh[j], &g_TAl[j]);
    } else if (idx < S2) {
        int j = idx - S1;
        int v = j >> 14, u = (j >> 7) & 127, w = j & 127;
        splitbf(Wt10[(u * 64 + v) * 128 + w], &g_TBh[j], &g_TBl[j]);
    }
}

__global__ void k_sp(const float* __restrict__ onehot, int* __restrict__ sp)
{
    int n = blockIdx.x * blockDim.x + threadIdx.x;
    if (n >= NN) return;
    const float* r = onehot + (size_t)n * NSP;
    int best = 0; float bv = r[0];
#pragma unroll
    for (int i = 1; i < NSP; i++) if (r[i] > bv) { bv = r[i]; best = i; }
    sp[n] = best;
}

// ---- projections ----
__global__ void k_proj_h(const float* __restrict__ nfh,
                         const float* __restrict__ Wh0, const float* __restrict__ Wh1,
                         float* __restrict__ hp0, float* __restrict__ hp1)
{
    int nb = blockIdx.x * 4, v = threadIdx.x;
    __shared__ float h0s[4][128], h1s[4][384];
    for (int i = v; i < 2048; i += 128) {
        int p = i >> 9, c = i & 511;
        float val = nfh[(size_t)(nb + p) * 512 + c];
        if (c < 128) h0s[p][c] = val; else h1s[p][c - 128] = val;
    }
    __syncthreads();
    float a0[4] = {}, a1[4][3] = {};
    for (int u = 0; u < 128; u++) {
        float w0 = Wh0[u * 128 + v], w1 = Wh1[u * 128 + v];
#pragma unroll
        for (int p = 0; p < 4; p++) {
            a0[p] += h0s[p][u] * w0;
            a1[p][0] += h1s[p][u * 3 + 0] * w1;
            a1[p][1] += h1s[p][u * 3 + 1] * w1;
            a1[p][2] += h1s[p][u * 3 + 2] * w1;
        }
    }
#pragma unroll
    for (int p = 0; p < 4; p++) {
        hp0[(size_t)(nb + p) * 128 + v] = a0[p] * INV_H;
#pragma unroll
        for (int i = 0; i < 3; i++)
            hp1[(size_t)(nb + p) * 384 + v * 3 + i] = a1[p][i] * INV_H;
    }
}

__global__ void k_proj_u(const float* __restrict__ nfu,
                         const float* __restrict__ Wu0, const float* __restrict__ Wu1,
                         float* __restrict__ up0, float* __restrict__ up1)
{
    int nb = blockIdx.x * 4, v = threadIdx.x;
    __shared__ float u0s[4][64], u1s[4][192];
    for (int i = v; i < 1024; i += 64) {
        int p = i >> 8, c = i & 255;
        float val = nfu[(size_t)(nb + p) * 256 + c];
        if (c < 64) u0s[p][c] = val; else u1s[p][c - 64] = val;
    }
    __syncthreads();
    float a0[4] = {}, a1[4][3] = {};
    for (int u = 0; u < 64; u++) {
        float w0 = Wu0[u * 64 + v], w1 = Wu1[u * 64 + v];
#pragma unroll
        for (int p = 0; p < 4; p++) {
            a0[p] += u0s[p][u] * w0;
            a1[p][0] += u1s[p][u * 3 + 0] * w1;
            a1[p][1] += u1s[p][u * 3 + 1] * w1;
            a1[p][2] += u1s[p][u * 3 + 2] * w1;
        }
    }
#pragma unroll
    for (int p = 0; p < 4; p++) {
        up0[(size_t)(nb + p) * 64 + v] = a0[p] * INV_U;
#pragma unroll
        for (int i = 0; i < 3; i++)
            up1[(size_t)(nb + p) * 192 + v * 3 + i] = a1[p][i] * INV_U;
    }
}

// ---- outer products -> A (pre-split bf16 hi/lo planes) ----
__global__ void k_xy(const float* __restrict__ hp0, const float* __restrict__ up0,
                     const float* __restrict__ hp1, const float* __restrict__ up1,
                     unsigned short* __restrict__ Ah, unsigned short* __restrict__ Al)
{
    int n = blockIdx.x, tid = threadIdx.x;
    __shared__ float h0s[128], u0s[64], h1s[384], u1s[192];
    if (tid < 128) h0s[tid] = hp0[(size_t)n * 128 + tid];
    else if (tid < 192) u0s[tid - 128] = up0[(size_t)n * 64 + tid - 128];
    for (int i = tid; i < 384; i += 256) h1s[i] = hp1[(size_t)n * 384 + i];
    if (tid < 192) u1s[tid] = up1[(size_t)n * 192 + tid];
    __syncthreads();
    unsigned* Ah32 = (unsigned*)(Ah + (size_t)n * 16384);
    unsigned* Al32 = (unsigned*)(Al + (size_t)n * 16384);
    for (int c2 = tid; c2 < 4096; c2 += 256) {
        int c = c2 * 2;
        int u = c >> 6, v = c & 63;
        // xy00 pair
        float a0 = h0s[u] * u0s[v];
        float a1 = h0s[u] * u0s[v + 1];
        unsigned h0b = (__float_as_uint(a0) + 0x8000u) & 0xFFFF0000u;
        unsigned h1b = (__float_as_uint(a1) + 0x8000u) & 0xFFFF0000u;
        Ah32[c2] = (h0b >> 16) | h1b;
        Al32[c2] = (unsigned)__bfloat16_as_ushort(__float2bfloat16_rn(a0 - __uint_as_float(h0b)))
                 | ((unsigned)__bfloat16_as_ushort(__float2bfloat16_rn(a1 - __uint_as_float(h1b))) << 16);
        // xy11 pair
        float b0 = h1s[u * 3] * u1s[v * 3] + h1s[u * 3 + 1] * u1s[v * 3 + 1]
                 + h1s[u * 3 + 2] * u1s[v * 3 + 2];
        float b1 = h1s[u * 3] * u1s[(v + 1) * 3] + h1s[u * 3 + 1] * u1s[(v + 1) * 3 + 1]
                 + h1s[u * 3 + 2] * u1s[(v + 1) * 3 + 2];
        unsigned g0b = (__float_as_uint(b0) + 0x8000u) & 0xFFFF0000u;
        unsigned g1b = (__float_as_uint(b1) + 0x8000u) & 0xFFFF0000u;
        Ah32[c2 + 4096] = (g0b >> 16) | g1b;
        Al32[c2 + 4096] = (unsigned)__bfloat16_as_ushort(__float2bfloat16_rn(b0 - __uint_as_float(g0b)))
                 | ((unsigned)__bfloat16_as_ushort(__float2bfloat16_rn(b1 - __uint_as_float(g1b))) << 16);
    }
}

// ---- bf16 3-term split tensor-core GEMM, 128x128x32 tiles ----
// PRESPLIT=1: A given as bf16 hi/lo planes (z0).  PRESPLIT=0: fp32 A, split on the fly.
// HALFOUT=1: C stored fp16.
#define LDSM4(R, addr) asm volatile( \
    "ldmatrix.sync.aligned.m8n8.x4.shared.b16 {%0,%1,%2,%3}, [%4];" \
    : "=r"((R)[0]), "=r"((R)[1]), "=r"((R)[2]), "=r"((R)[3]) : "r"(addr))
#define LDSM4T(R0,R1,R2,R3, addr) asm volatile( \
    "ldmatrix.sync.aligned.m8n8.x4.trans.shared.b16 {%0,%1,%2,%3}, [%4];" \
    : "=r"(R0), "=r"(R1), "=r"(R2), "=r"(R3) : "r"(addr))
#define MMAB(Cv, Av, Bv) asm volatile( \
    "mma.sync.aligned.m16n8k16.row.col.f32.bf16.bf16.f32 " \
    "{%0,%1,%2,%3},{%4,%5,%6,%7},{%8,%9},{%0,%1,%2,%3};" \
    : "+f"((Cv)[0]), "+f"((Cv)[1]), "+f"((Cv)[2]), "+f"((Cv)[3]) \
    : "r"((Av)[0]), "r"((Av)[1]), "r"((Av)[2]), "r"((Av)[3]), "r"((Bv)[0]), "r"((Bv)[1]))

template <int PRESPLIT, int HALFOUT>
__global__ __launch_bounds__(256, 2)
void k_mma(const float* __restrict__ A,
           const unsigned short* __restrict__ Aph, const unsigned short* __restrict__ Apl,
           int lda,
           const unsigned short* __restrict__ Bh, const unsigned short* __restrict__ Bl,
           int ldb, void* __restrict__ Cv, int ldc, int Ktot, size_t partStride)
{
    __shared__ __align__(16) unsigned short sAh[128][40], sAl[128][40];
    __shared__ __align__(16) unsigned short sBh[32][136], sBl[32][136];
    const int kLen = Ktot / gridDim.z;
    const int kOff = blockIdx.z * kLen;
    const int m0 = blockIdx.x * 128, c0 = blockIdx.y * 128;
    const int tid = threadIdx.x, lane = tid & 31, wid = tid >> 5;
    const int wm = wid & 1, wn = wid >> 1;
    const int ar = tid >> 1, ac = (tid & 1) << 4;

    unsigned aHiB = (unsigned)__cvta_generic_to_shared(&sAh[0][0]);
    unsigned aLoB = (unsigned)__cvta_generic_to_shared(&sAl[0][0]);
    unsigned bHiB = (unsigned)__cvta_generic_to_shared(&sBh[0][0]);
    unsigned bLoB = (unsigned)__cvta_generic_to_shared(&sBl[0][0]);
    unsigned aOff = (unsigned)(((wm * 64 + (lane & 15)) * 40 + (lane >> 4) * 8) * 2);
    unsigned bOff = (unsigned)(((lane & 15) * 136 + wn * 32 + (lane >> 4) * 8) * 2);
    const unsigned aHi = aHiB + aOff, aLo = aLoB + aOff;
    const unsigned bHi = bHiB + bOff, bLo = bLoB + bOff;

    float c[4][4][4];
#pragma unroll
    for (int a = 0; a < 4; a++)
#pragma unroll
        for (int b = 0; b < 4; b++)
#pragma unroll
            for (int d = 0; d < 4; d++) c[a][b][d] = 0.f;

    for (int kt = 0; kt < kLen; kt += 32) {
        const int k0 = kOff + kt;
        if (PRESPLIT) {
            const unsigned short* ph = Aph + (size_t)(m0 + ar) * lda + k0 + ac;
            const unsigned short* pl = Apl + (size_t)(m0 + ar) * lda + k0 + ac;
            *(uint4*)&sAh[ar][ac]     = *(const uint4*)(ph);
            *(uint4*)&sAh[ar][ac + 8] = *(const uint4*)(ph + 8);
            *(uint4*)&sAl[ar][ac]     = *(const uint4*)(pl);
            *(uint4*)&sAl[ar][ac + 8] = *(const uint4*)(pl + 8);
        } else {
#pragma unroll
            for (int q = 0; q < 16; q += 4) {
                float4 v = *(const float4*)&A[(size_t)(m0 + ar) * lda + k0 + ac + q];
                unsigned h0 = (__float_as_uint(v.x) + 0x8000u) & 0xFFFF0000u;
                unsigned h1 = (__float_as_uint(v.y) + 0x8000u) & 0xFFFF0000u;
                unsigned h2 = (__float_as_uint(v.z) + 0x8000u) & 0xFFFF0000u;
                unsigned h3 = (__float_as_uint(v.w) + 0x8000u) & 0xFFFF0000u;
                *(unsigned*)&sAh[ar][ac + q]     = (h0 >> 16) | h1;
                *(unsigned*)&sAh[ar][ac + q + 2] = (h2 >> 16) | h3;
                unsigned l01 = (unsigned)__bfloat16_as_ushort(__float2bfloat16_rn(v.x - __uint_as_float(h0)))
                    | ((unsigned)__bfloat16_as_ushort(__float2bfloat16_rn(v.y - __uint_as_float(h1))) << 16);
                unsigned l23 = (unsigned)__bfloat16_as_ushort(__float2bfloat16_rn(v.z - __uint_as_float(h2)))
                    | ((unsigned)__bfloat16_as_ushort(__float2bfloat16_rn(v.w - __uint_as_float(h3))) << 16);
                *(unsigned*)&sAl[ar][ac + q]     = l01;
                *(unsigned*)&sAl[ar][ac + q + 2] = l23;
            }
        }
#pragma unroll
        for (int cb = 0; cb < 2; cb++) {
            int i = tid + (cb << 8);
            int rr = i >> 4, c8 = (i & 15) << 3;
            *(uint4*)&sBh[rr][c8] = *(const uint4*)&Bh[(size_t)(k0 + rr) * ldb + c0 + c8];
            *(uint4*)&sBl[rr][c8] = *(const uint4*)&Bl[(size_t)(k0 + rr) * ldb + c0 + c8];
        }
        __syncthreads();
#pragma unroll
        for (int kf = 0; kf < 2; kf++) {
            unsigned Af[4][4], Bf[4][2];
#pragma unroll
            for (int mf = 0; mf < 4; mf++) LDSM4(Af[mf], aHi + mf * 1280 + kf * 32);
#pragma unroll
            for (int nq = 0; nq < 2; nq++) {
                unsigned r0, r1, r2, r3;
                LDSM4T(r0, r1, r2, r3, bHi + kf * 4352 + nq * 32);
                Bf[2 * nq][0] = r0; Bf[2 * nq][1] = r1;
                Bf[2 * nq + 1][0] = r2; Bf[2 * nq + 1][1] = r3;
            }
#pragma unroll
            for (int mf = 0; mf < 4; mf++)
#pragma unroll
                for (int nf = 0; nf < 4; nf++) MMAB(c[mf][nf], Af[mf], Bf[nf]);
#pragma unroll
            for (int mf = 0; mf < 4; mf++) LDSM4(Af[mf], aLo + mf * 1280 + kf * 32);
#pragma unroll
            for (int mf = 0; mf < 4; mf++)
#pragma unroll
                for (int nf = 0; nf < 4; nf++) MMAB(c[mf][nf], Af[mf], Bf[nf]);
#pragma unroll
            for (int mf = 0; mf < 4; mf++) LDSM4(Af[mf], aHi + mf * 1280 + kf * 32);
#pragma unroll
            for (int nq = 0; nq < 2; nq++) {
                unsigned r0, r1, r2, r3;
                LDSM4T(r0, r1, r2, r3, bLo + kf * 4352 + nq * 32);
                Bf[2 * nq][0] = r0; Bf[2 * nq][1] = r1;
                Bf[2 * nq + 1][0] = r2; Bf[2 * nq + 1][1] = r3;
            }
#pragma unroll
            for (int mf = 0; mf < 4; mf++)
#pragma unroll
                for (int nf = 0; nf < 4; nf++) MMAB(c[mf][nf], Af[mf], Bf[nf]);
        }
        __syncthreads();
    }
    int gq = lane >> 2, t4 = lane & 3;
    if (HALFOUT) {
        __half* C = (__half*)Cv;
#pragma unroll
        for (int mf = 0; mf < 4; mf++)
#pragma unroll
            for (int nf = 0; nf < 4; nf++) {
                int row = m0 + wm * 64 + mf * 16 + gq;
                int col = c0 + wn * 32 + nf * 8 + t4 * 2;
                *(__half2*)&C[(size_t)row * ldc + col] =
                    __floats2half2_rn(c[mf][nf][0], c[mf][nf][1]);
                *(__half2*)&C[(size_t)(row + 8) * ldc + col] =
                    __floats2half2_rn(c[mf][nf][2], c[mf][nf][3]);
            }
    } else {
        float* C = (float*)Cv + (size_t)blockIdx.z * partStride;
#pragma unroll
        for (int mf = 0; mf < 4; mf++)
#pragma unroll
            for (int nf = 0; nf < 4; nf++) {
                int row = m0 + wm * 64 + mf * 16 + gq;
                int col = c0 + wn * 32 + nf * 8 + t4 * 2;
                *(float2*)&C[(size_t)row * ldc + col] = make_float2(c[mf][nf][0], c[mf][nf][1]);
                *(float2*)&C[(size_t)(row + 8) * ldc + col] = make_float2(c[mf][nf][2], c[mf][nf][3]);
            }
    }
}

// ---- z0 reduce + activations ----
__global__ void k_z0act(const float* __restrict__ P, float* __restrict__ s, float* __restrict__ g)
{
    int idx = blockIdx.x * blockDim.x + threadIdx.x;
    if (idx >= NN * 128) return;
    int n = idx >> 7, w = idx & 127;
    const size_t S = (size_t)NN * 256;
    size_t base = (size_t)n * 256;
    float za = (P[base + w] + P[S + base + w] + P[2 * S + base + w] + P[3 * S + base + w]) * INV_TP;
    float zb = (P[base + 128 + w] + P[S + base + 128 + w] + P[2 * S + base + 128 + w] + P[3 * S + base + 128 + w]) * INV_TP;
    s[idx] = za / (1.0f + __expf(-za));
    g[idx] = 1.0f / (1.0f + __expf(-zb));
}

// ---- z1 + gate (reads fp16 ta/tb) ----
__global__ void k_z1v(const unsigned short* __restrict__ ta, const unsigned short* __restrict__ tb,
                      const float* __restrict__ hp1, const float* __restrict__ up1,
                      const float* __restrict__ gg, float* __restrict__ vmat)
{
    int n = blockIdx.x, w = threadIdx.x;
    __shared__ float u1s[192], h1s[384];
    for (int i = w; i < 192; i += 128) u1s[i] = up1[(size_t)n * 192 + i];
    for (int i = w; i < 384; i += 128) h1s[i] = hp1[(size_t)n * 384 + i];
    __syncthreads();
    float a0 = 0.f, a1 = 0.f, a2 = 0.f;
    const __half* tap = (const __half*)ta + (size_t)n * 8192 + w;
    for (int v = 0; v < 64; v++) {
        float t = __half2float(tap[v * 128]);
        a0 += t * u1s[v * 3]; a1 += t * u1s[v * 3 + 1]; a2 += t * u1s[v * 3 + 2];
    }
    const __half* tbp = (const __half*)tb + (size_t)n * 16384 + w;
    for (int u = 0; u < 128; u++) {
        float t = __half2float(tbp[u * 128]);
        a0 += t * h1s[u * 3]; a1 += t * h1s[u * 3 + 1]; a2 += t * h1s[u * 3 + 2];
    }
    float gv = gg[(size_t)n * 128 + w];
    vmat[(size_t)n * 384 + w * 3 + 0] = a0 * INV_TP * gv;
    vmat[(size_t)n * 384 + w * 3 + 1] = a1 * INV_TP * gv;
    vmat[(size_t)n * 384 + w * 3 + 2] = a2 * INV_TP * gv;
}

// ---- y0 ----
__global__ void k_y0(const float* __restrict__ s, const float* __restrict__ nfh,
                     const int* __restrict__ sp, const float* __restrict__ Wp0,
                     const float* __restrict__ bp0, const float* __restrict__ Wsc0,
                     float* __restrict__ y0)
{
    int nb = blockIdx.x * 4, w = threadIdx.x;
    __shared__ float ss[4][128], h0s[4][128];
    __shared__ int sps[4];
    for (int i = w; i < 512; i += 128) {
        int p = i >> 7, c = i & 127;
        ss[p][c] = s[(size_t)(nb + p) * 128 + c];
        h0s[p][c] = nfh[(size_t)(nb + p) * 512 + c];
    }
    if (w < 4) sps[w] = sp[nb + w];
    __syncthreads();
    float a[4] = {}, b[4] = {};
    for (int u = 0; u < 128; u++) {
        float wp = Wp0[u * 128 + w];
#pragma unroll
        for (int p = 0; p < 4; p++) a[p] += ss[p][u] * wp;
#pragma unroll
        for (int p = 0; p < 4; p++) b[p] += h0s[p][u] * Wsc0[u * 1280 + sps[p] * 128 + w];
    }
    float bp = bp0[w];
#pragma unroll
    for (int p = 0; p < 4; p++)
        y0[(size_t)(nb + p) * 128 + w] = a[p] * INV_H + bp + b[p] * INV_SC;
}

// ---- y1 ----
__global__ void k_y1(const float* __restrict__ vmat, const float* __restrict__ nfh,
                     const int* __restrict__ sp, const float* __restrict__ Wp1,
                     const float* __restrict__ Wsc1, float* __restrict__ y1)
{
    int nb = blockIdx.x * 2, w = threadIdx.x;
    __shared__ float vs[2][384], h1s[2][384];
    __shared__ int sps[2];
    for (int i = w; i < 768; i += 128) {
        int p = i / 384, c = i % 384;
        vs[p][c] = vmat[(size_t)(nb + p) * 384 + c];
        h1s[p][c] = nfh[(size_t)(nb + p) * 512 + 128 + c];
    }
    if (w < 2) sps[w] = sp[nb + w];
    __syncthreads();
    float a[2][3] = {}, b[2][3] = {};
    for (int u = 0; u < 128; u++) {
        float wp = Wp1[u * 128 + w];
#pragma unroll
        for (int p = 0; p < 2; p++) {
            a[p][0] += vs[p][u * 3] * wp;
            a[p][1] += vs[p][u * 3 + 1] * wp;
            a[p][2] += vs[p][u * 3 + 2] * wp;
        }
#pragma unroll
        for (int p = 0; p < 2; p++) {
            float wsc = Wsc1[u * 1280 + sps[p] * 128 + w];
            b[p][0] += h1s[p][u * 3] * wsc;
            b[p][1] += h1s[p][u * 3 + 1] * wsc;
            b[p][2] += h1s[p][u * 3 + 2] * wsc;
        }
    }
#pragma unroll
    for (int p = 0; p < 2; p++)
#pragma unroll
        for (int i = 0; i < 3; i++)
            y1[(size_t)(nb + p) * 384 + w * 3 + i] = a[p][i] * INV_H + b[p][i] * INV_SC;
}

// ---- deterministic group stats ----
__device__ __forceinline__ int lowerBound(const int* b, int n, int val)
{
    int lo = 0, hi = n;
    while (lo < hi) { int mid = (lo + hi) >> 1; if (b[mid] < val) lo = mid + 1; else hi = mid; }
    return lo;
}

__global__ void k_stats(const float* __restrict__ y0, const float* __restrict__ y1,
                        const int* __restrict__ batch,
                        float* __restrict__ mean0, float* __restrict__ rs0, float* __restrict__ rs1)
{
    int g = blockIdx.x, tid = threadIdx.x;
    int lo = lowerBound(batch, NN, g);
    int hi = lowerBound(batch, NN, g + 1);
    int cntI = hi - lo;
    float cnt = cntI < 1 ? 1.0f : (float)cntI;
    double s0 = 0.0, q0 = 0.0, q1 = 0.0;
    for (int j = tid; j < cntI * 128; j += 256) {
        float v = y0[(size_t)lo * 128 + j];
        s0 += v; q0 += (double)v * v;
    }
    for (int j = tid; j < cntI * 384; j += 256) {
        float v = y1[(size_t)lo * 384 + j];
        q1 += (double)v * v;
    }
    __shared__ double r0[256], r1[256], r2[256];
    r0[tid] = s0; r1[tid] = q0; r2[tid] = q1;
    __syncthreads();
    for (int off = 128; off > 0; off >>= 1) {
        if (tid < off) { r0[tid] += r0[tid + off]; r1[tid] += r1[tid + off]; r2[tid] += r2[tid + off]; }
        __syncthreads();
    }
    if (tid == 0) {
        double m = r0[0] / ((double)cnt * 128.0);
        double v0 = r1[0] / ((double)cnt * 128.0) - m * m;
        if (v0 < 0.0) v0 = 0.0;
        double v1 = r2[0] / ((double)cnt * 384.0);
        mean0[g] = (float)m;
        rs0[g] = 1.0f / (sqrtf((float)v0) + EPSF);
        rs1[g] = 1.0f / (sqrtf((float)v1) + EPSF);
    }
}

// ---- final output ----
__global__ void k_out(const float* __restrict__ nfh, const int* __restrict__ batch,
                      const float* __restrict__ y0, const float* __restrict__ y1,
                      const float* __restrict__ mean0, const float* __restrict__ rs0,
                      const float* __restrict__ rs1,
                      const float* __restrict__ Ws0, const float* __restrict__ bs0,
                      const float* __restrict__ Ws1,
                      const float* __restrict__ lnw0, const float* __restrict__ lnb0,
                      const float* __restrict__ lnw1, float* __restrict__ out)
{
    int nb = blockIdx.x * 2, w = threadIdx.x;
    __shared__ float h0s[2][128], h1s[2][384];
    for (int i = w; i < 1024; i += 128) {
        int p = i >> 9, c = i & 511;
        float val = nfh[(size_t)(nb + p) * 512 + c];
        if (c < 128) h0s[p][c] = val; else h1s[p][c - 128] = val;
    }
    __syncthreads();
    float o0[2] = {}, o1[2][3] = {};
    for (int u = 0; u < 128; u++) {
        float w0 = Ws0[u * 128 + w], w1 = Ws1[u * 128 + w];
#pragma unroll
        for (int p = 0; p < 2; p++) {
            o0[p] += h0s[p][u] * w0;
            o1[p][0] += h1s[p][u * 3] * w1;
            o1[p][1] += h1s[p][u * 3 + 1] * w1;
            o1[p][2] += h1s[p][u * 3 + 2] * w1;
        }
    }
    float lw0 = lnw0[w], lb0 = lnb0[w], lw1 = lnw1[w], bsw = bs0[w];
#pragma unroll
    for (int p = 0; p < 2; p++) {
        int n = nb + p, b = batch[n];
        float m = mean0[b], r0v = rs0[b], r1v = rs1[b];
        out[(size_t)n * 512 + w] =
            (y0[(size_t)n * 128 + w] - m) * r0v * lw0 + lb0 + o0[p] * INV_H + bsw;
#pragma unroll
        for (int i = 0; i < 3; i++)
            out[(size_t)n * 512 + 128 + w * 3 + i] =
                y1[(size_t)n * 384 + w * 3 + i] * r1v * lw1 + o1[p][i] * INV_H;
    }
}

// ---- host launcher ----
static void* sym(const void* s) { void* p = nullptr; cudaGetSymbolAddress(&p, s); return p; }

extern "C" void kernel_launch(void* const* d_in, const int* in_sizes, int n_in,
                              void* d_out, int out_size)
{
    const float* nfh  = (const float*)d_in[0];
    const float* nfu  = (const float*)d_in[1];
    const float* oneh = (const float*)d_in[2];
    const int* batch  = (const int*)d_in[3];
    const float* Wh0  = (const float*)d_in[4];
    const float* Wh1  = (const float*)d_in[5];
    const float* Wu0  = (const float*)d_in[6];
    const float* Wu1  = (const float*)d_in[7];
    const float* Wt00 = (const float*)d_in[8];
    const float* Wt11 = (const float*)d_in[9];
    const float* Wt01 = (const float*)d_in[10];
    const float* Wt10 = (const float*)d_in[11];
    const float* Wp0  = (const float*)d_in[12];
    const float* bp0  = (const float*)d_in[13];
    const float* Wp1  = (const float*)d_in[14];
    const float* Wsc0 = (const float*)d_in[15];
    const float* Wsc1 = (const float*)d_in[16];
    const float* lnw0 = (const float*)d_in[17];
    const float* lnb0 = (const float*)d_in[18];
    const float* lnw1 = (const float*)d_in[19];
    const float* Ws0  = (const float*)d_in[20];
    const float* bs0  = (const float*)d_in[21];
    const float* Ws1  = (const float*)d_in[22];
    float* out = (float*)d_out;

    float* hp0  = (float*)sym(g_hp0);
    float* hp1  = (float*)sym(g_hp1);
    float* up0  = (float*)sym(g_up0);
    float* up1  = (float*)sym(g_up1);
    unsigned short* Ah = (unsigned short*)sym(g_Ah);
    unsigned short* Al = (unsigned short*)sym(g_Al);
    unsigned short* B0h = (unsigned short*)sym(g_B0h);
    unsigned short* B0l = (unsigned short*)sym(g_B0l);
    unsigned short* TAh = (unsigned short*)sym(g_TAh);
    unsigned short* TAl = (unsigned short*)sym(g_TAl);
    unsigned short* TBh = (unsigned short*)sym(g_TBh);
    unsigned short* TBl = (unsigned short*)sym(g_TBl);
    float* z0p  = (float*)sym(g_z0p);
    float* sbuf = (float*)sym(g_s);
    float* gbuf = (float*)sym(g_g);
    unsigned short* tab = (unsigned short*)sym(g_ta);
    unsigned short* tbb = (unsigned short*)sym(g_tb);
    float* vmat = (float*)sym(g_vmat);
    float* y0b  = (float*)sym(g_y0);
    float* y1b  = (float*)sym(g_y1);
    int*   spb  = (int*)sym(g_spi);
    float* mean0 = (float*)sym(g_mean0);
    float* rs0  = (float*)sym(g_rs0);
    float* rs1  = (float*)sym(g_rs1);

    k_prep<<<24576, 256>>>(Wt00, Wt11, Wt01, Wt10);
    k_sp<<<16, 256>>>(oneh, spb);
    k_proj_h<<<NN / 4, 128>>>(nfh, Wh0, Wh1, hp0, hp1);
    k_proj_u<<<NN / 4, 64>>>(nfu, Wu0, Wu1, up0, up1);
    k_xy<<<NN, 256>>>(hp0, up0, hp1, up1, Ah, Al);
    {   // z0: (4096x16384)@(16384x256), split-K=4, pre-split A
        dim3 grid(32, 2, 4);
        k_mma<1, 0><<<grid, 256>>>(nullptr, Ah, Al, 16384, B0h, B0l, 256,
                                   z0p, 256, 16384, (size_t)NN * 256);
    }
    k_z0act<<<(NN * 128 + 255) / 256, 256>>>(z0p, sbuf, gbuf);
    {   // ta: (4096x128)@(128x8192), fp16 out
        dim3 grid(32, 64, 1);
        k_mma<0, 1><<<grid, 256>>>(hp0, nullptr, nullptr, 128, TAh, TAl, 8192,
                                   tab, 8192, 128, 0);
    }
    {   // tb: (4096x64)@(64x16384), fp16 out
        dim3 grid(32, 128, 1);
        k_mma<0, 1><<<grid, 256>>>(up0, nullptr, nullptr, 64, TBh, TBl, 16384,
                                   tbb, 16384, 64, 0);
    }
    k_z1v<<<NN, 128>>>(tab, tbb, hp1, up1, gbuf, vmat);
    k_y0<<<NN / 4, 128>>>(sbuf, nfh, spb, Wp0, bp0, Wsc0, y0b);
    k_y1<<<NN / 2, 128>>>(vmat, nfh, spb, Wp1, Wsc1, y1b);
    k_stats<<<NG, 256>>>(y0b, y1b, batch, mean0, rs0, rs1);
    k_out<<<NN / 2, 128>>>(nfh, batch, y0b, y1b, mean0, rs0, rs1,
                           Ws0, bs0, Ws1, lnw0, lnb0, lnw1, out);
}

// round 12
// speedup vs baseline: 1.4418x; 1.4418x over previous
#include <cuda_runtime.h>
#include <cuda_bf16.h>
#include <stdint.h>
#include <math.h>

#define NN   4096
#define NG   64
#define NSP  10
#define EPSF 1e-5f
#define INV_H  0.08838834764831845f
#define INV_U  0.125f
#define INV_TP 0.0078125f
#define INV_SC 0.02795084971874737f
#define ISQRT3 0.57735026918962576f

// ---- static scratch ----
static __device__ float g_hp0[NN * 128];
static __device__ float g_hp1[NN * 384];
static __device__ float g_up0[NN * 64];
static __device__ float g_up1[NN * 192];
static __device__ float g_A[(size_t)NN * 16384];
static __device__ unsigned short g_B0h[16384 * 256], g_B0l[16384 * 256];
static __device__ unsigned short g_TAh[128 * 8192],  g_TAl[128 * 8192];
static __device__ unsigned short g_TBh[64 * 16384],  g_TBl[64 * 16384];
static __device__ float g_z0p[(size_t)4 * NN * 256];
static __device__ float g_s[NN * 128];
static __device__ float g_g[NN * 128];
static __device__ float g_ta[(size_t)NN * 8192];
static __device__ float g_tb[(size_t)NN * 16384];
static __device__ float g_vmat[NN * 384];
static __device__ float g_y0[NN * 128];
static __device__ float g_y1[NN * 384];
static __device__ int   g_spi[NN];
static __device__ float g_mean0[NG], g_rs0[NG], g_rs1[NG];

__device__ __forceinline__ void splitbf(float w, unsigned short* h, unsigned short* l)
{
    unsigned hi = (__float_as_uint(w) + 0x8000u) & 0xFFFF0000u;
    *h = (unsigned short)(hi >> 16);
    *l = __bfloat16_as_ushort(__float2bfloat16_rn(w - __uint_as_float(hi)));
}

// ---- prep: split B matrices to bf16 hi/lo ----
__global__ void k_prep(const float* __restrict__ Wt00, const float* __restrict__ Wt11,
                       const float* __restrict__ Wt01, const float* __restrict__ Wt10)
{
    const int S0 = 16384 * 256, S1 = S0 + 128 * 8192, S2 = S1 + 64 * 16384;
    int idx = blockIdx.x * blockDim.x + threadIdx.x;
    if (idx < S0) {
        int k = idx >> 8;
        float w = (k < 8192) ? Wt00[idx] : Wt11[idx - 2097152] * ISQRT3;
        splitbf(w, &g_B0h[idx], &g_B0l[idx]);
    } else if (idx < S1) {
        int j = idx - S0;
        splitbf(Wt01[j], &g_TAh[j], &g_TAl[j]);
    } else if (idx < S2) {
        int j = idx - S1;
        int v = j >> 14, u = (j >> 7) & 127, w = j & 127;
        splitbf(Wt10[(u * 64 + v) * 128 + w], &g_TBh[j], &g_TBl[j]);
    }
}

__global__ void k_sp(const float* __restrict__ onehot, int* __restrict__ sp)
{
    int n = blockIdx.x * blockDim.x + threadIdx.x;
    if (n >= NN) return;
    const float* r = onehot + (size_t)n * NSP;
    int best = 0; float bv = r[0];
#pragma unroll
    for (int i = 1; i < NSP; i++) if (r[i] > bv) { bv = r[i]; best = i; }
    sp[n] = best;
}

// ---- projections ----
__global__ void k_proj_h(const float* __restrict__ nfh,
                         const float* __restrict__ Wh0, const float* __restrict__ Wh1,
                         float* __restrict__ hp0, float* __restrict__ hp1)
{
    int nb = blockIdx.x * 4, v = threadIdx.x;
    __shared__ float h0s[4][128], h1s[4][384];
    for (int i = v; i < 2048; i += 128) {
        int p = i >> 9, c = i & 511;
        float val = nfh[(size_t)(nb + p) * 512 + c];
        if (c < 128) h0s[p][c] = val; else h1s[p][c - 128] = val;
    }
    __syncthreads();
    float a0[4] = {}, a1[4][3] = {};
    for (int u = 0; u < 128; u++) {
        float w0 = Wh0[u * 128 + v], w1 = Wh1[u * 128 + v];
#pragma unroll
        for (int p = 0; p < 4; p++) {
            a0[p] += h0s[p][u] * w0;
            a1[p][0] += h1s[p][u * 3 + 0] * w1;
            a1[p][1] += h1s[p][u * 3 + 1] * w1;
            a1[p][2] += h1s[p][u * 3 + 2] * w1;
        }
    }
#pragma unroll
    for (int p = 0; p < 4; p++) {
        hp0[(size_t)(nb + p) * 128 + v] = a0[p] * INV_H;
#pragma unroll
        for (int i = 0; i < 3; i++)
            hp1[(size_t)(nb + p) * 384 + v * 3 + i] = a1[p][i] * INV_H;
    }
}

__global__ void k_proj_u(const float* __restrict__ nfu,
                         const float* __restrict__ Wu0, const float* __restrict__ Wu1,
                         float* __restrict__ up0, float* __restrict__ up1)
{
    int nb = blockIdx.x * 4, v = threadIdx.x;
    __shared__ float u0s[4][64], u1s[4][192];
    for (int i = v; i < 1024; i += 64) {
        int p = i >> 8, c = i & 255;
        float val = nfu[(size_t)(nb + p) * 256 + c];
        if (c < 64) u0s[p][c] = val; else u1s[p][c - 64] = val;
    }
    __syncthreads();
    float a0[4] = {}, a1[4][3] = {};
    for (int u = 0; u < 64; u++) {
        float w0 = Wu0[u * 64 + v], w1 = Wu1[u * 64 + v];
#pragma unroll
        for (int p = 0; p < 4; p++) {
            a0[p] += u0s[p][u] * w0;
            a1[p][0] += u1s[p][u * 3 + 0] * w1;
            a1[p][1] += u1s[p][u * 3 + 1] * w1;
            a1[p][2] += u1s[p][u * 3 + 2] * w1;
        }
    }
#pragma unroll
    for (int p = 0; p < 4; p++) {
        up0[(size_t)(nb + p) * 64 + v] = a0[p] * INV_U;
#pragma unroll
        for (int i = 0; i < 3; i++)
            up1[(size_t)(nb + p) * 192 + v * 3 + i] = a1[p][i] * INV_U;
    }
}

// ---- outer products -> A (fp32, as R5) ----
__global__ void k_xy(const float* __restrict__ hp0, const float* __restrict__ up0,
                     const float* __restrict__ hp1, const float* __restrict__ up1,
                     float* __restrict__ A)
{
    int n = blockIdx.x, tid = threadIdx.x;
    __shared__ float h0s[128], u0s[64], h1s[384], u1s[192];
    if (tid < 128) h0s[tid] = hp0[(size_t)n * 128 + tid];
    else if (tid < 192) u0s[tid - 128] = up0[(size_t)n * 64 + tid - 128];
    for (int i = tid; i < 384; i += 256) h1s[i] = hp1[(size_t)n * 384 + i];
    if (tid < 192) u1s[tid] = up1[(size_t)n * 192 + tid];
    __syncthreads();
    float* Ar = A + (size_t)n * 16384;
    for (int c = tid; c < 8192; c += 256) {
        int u = c >> 6, v = c & 63;
        Ar[c] = h0s[u] * u0s[v];
        Ar[c + 8192] = h1s[u * 3] * u1s[v * 3] + h1s[u * 3 + 1] * u1s[v * 3 + 1]
                     + h1s[u * 3 + 2] * u1s[v * 3 + 2];
    }
}

// ---- pipelined bf16 3-term split HMMA GEMM, 128x128x32 tiles, double-buffered ----
#define LDSM4(R, addr) asm volatile( \
    "ldmatrix.sync.aligned.m8n8.x4.shared.b16 {%0,%1,%2,%3}, [%4];" \
    : "=r"((R)[0]), "=r"((R)[1]), "=r"((R)[2]), "=r"((R)[3]) : "r"(addr))
#define LDSM4T(R0,R1,R2,R3, addr) asm volatile( \
    "ldmatrix.sync.aligned.m8n8.x4.trans.shared.b16 {%0,%1,%2,%3}, [%4];" \
    : "=r"(R0), "=r"(R1), "=r"(R2), "=r"(R3) : "r"(addr))
#define MMAB(Cv, Av, Bv) asm volatile( \
    "mma.sync.aligned.m16n8k16.row.col.f32.bf16.bf16.f32 " \
    "{%0,%1,%2,%3},{%4,%5,%6,%7},{%8,%9},{%0,%1,%2,%3};" \
    : "+f"((Cv)[0]), "+f"((Cv)[1]), "+f"((Cv)[2]), "+f"((Cv)[3]) \
    : "r"((Av)[0]), "r"((Av)[1]), "r"((Av)[2]), "r"((Av)[3]), "r"((Bv)[0]), "r"((Bv)[1]))
#define CPA16(dst, src) asm volatile( \
    "cp.async.cg.shared.global [%0], [%1], 16;" :: "r"(dst), "l"(src))

__device__ __forceinline__ void mma_tile(unsigned aHi, unsigned aLo,
                                         unsigned bHi, unsigned bLo, float c[4][4][4])
{
#pragma unroll
    for (int kf = 0; kf < 2; kf++) {
        unsigned Af[4][4], Bf[4][2];
#pragma unroll
        for (int mf = 0; mf < 4; mf++) LDSM4(Af[mf], aHi + mf * 1280 + kf * 32);
#pragma unroll
        for (int nq = 0; nq < 2; nq++) {
            unsigned r0, r1, r2, r3;
            LDSM4T(r0, r1, r2, r3, bHi + kf * 4352 + nq * 32);
            Bf[2 * nq][0] = r0; Bf[2 * nq][1] = r1;
            Bf[2 * nq + 1][0] = r2; Bf[2 * nq + 1][1] = r3;
        }
#pragma unroll
        for (int mf = 0; mf < 4; mf++)
#pragma unroll
            for (int nf = 0; nf < 4; nf++) MMAB(c[mf][nf], Af[mf], Bf[nf]);
#pragma unroll
        for (int mf = 0; mf < 4; mf++) LDSM4(Af[mf], aLo + mf * 1280 + kf * 32);
#pragma unroll
        for (int mf = 0; mf < 4; mf++)
#pragma unroll
            for (int nf = 0; nf < 4; nf++) MMAB(c[mf][nf], Af[mf], Bf[nf]);
#pragma unroll
        for (int mf = 0; mf < 4; mf++) LDSM4(Af[mf], aHi + mf * 1280 + kf * 32);
#pragma unroll
        for (int nq = 0; nq < 2; nq++) {
            unsigned r0, r1, r2, r3;
            LDSM4T(r0, r1, r2, r3, bLo + kf * 4352 + nq * 32);
            Bf[2 * nq][0] = r0; Bf[2 * nq][1] = r1;
            Bf[2 * nq + 1][0] = r2; Bf[2 * nq + 1][1] = r3;
        }
#pragma unroll
        for (int mf = 0; mf < 4; mf++)
#pragma unroll
            for (int nf = 0; nf < 4; nf++) MMAB(c[mf][nf], Af[mf], Bf[nf]);
    }
}

// smem layout (halfs): sAh[2][5120] | sAl[2][5120] | sBh[2][4352] | sBl[2][4352]
#define SMEM_MMA_BYTES ((2 * 5120 + 2 * 5120 + 2 * 4352 + 2 * 4352) * 2)

__global__ __launch_bounds__(256, 2)
void k_mma(const float* __restrict__ A, int lda,
           const unsigned short* __restrict__ Bh, const unsigned short* __restrict__ Bl,
           int ldb, float* __restrict__ C, int ldc, int Ktot, size_t partStride)
{
    extern __shared__ __align__(16) unsigned short sm[];
    unsigned short* sAh = sm;            // 2 x 5120
    unsigned short* sAl = sm + 10240;
    unsigned short* sBh = sm + 20480;    // 2 x 4352
    unsigned short* sBl = sm + 29184;
    const int kLen = Ktot / gridDim.z;
    const int kOff = blockIdx.z * kLen;
    const int nt = kLen >> 5;
    const int m0 = blockIdx.x * 128, c0 = blockIdx.y * 128;
    const int tid = threadIdx.x, lane = tid & 31, wid = tid >> 5;
    const int wm = wid & 1, wn = wid >> 1;
    const int ar = tid >> 1, ac = (tid & 1) << 4;

    const unsigned aHiB = (unsigned)__cvta_generic_to_shared(sAh);
    const unsigned aLoB = (unsigned)__cvta_generic_to_shared(sAl);
    const unsigned bHiB = (unsigned)__cvta_generic_to_shared(sBh);
    const unsigned bLoB = (unsigned)__cvta_generic_to_shared(sBl);
    const unsigned aOff = (unsigned)(((wm * 64 + (lane & 15)) * 40 + (lane >> 4) * 8) * 2);
    const unsigned bOff = (unsigned)(((lane & 15) * 136 + wn * 32 + (lane >> 4) * 8) * 2);
    // B load (cp.async) per-thread targets
    const int bi0r = tid >> 4, bi0c = (tid & 15) << 3;
    const int bi1r = (tid + 256) >> 4, bi1c = ((tid + 256) & 15) << 3;

    float c[4][4][4];
#pragma unroll
    for (int a = 0; a < 4; a++)
#pragma unroll
        for (int b = 0; b < 4; b++)
#pragma unroll
            for (int d = 0; d < 4; d++) c[a][b][d] = 0.f;

    float4 av[4];

#define LOADA(k0) do { \
    const float* ap_ = &A[(size_t)(m0 + ar) * lda + (k0) + ac]; \
    av[0] = *(const float4*)(ap_); \
    av[1] = *(const float4*)(ap_ + 4); \
    av[2] = *(const float4*)(ap_ + 8); \
    av[3] = *(const float4*)(ap_ + 12); \
} while (0)

#define STOREA(buf) do { \
    unsigned short* dh_ = sAh + (buf) * 5120 + ar * 40 + ac; \
    unsigned short* dl_ = sAl + (buf) * 5120 + ar * 40 + ac; \
    _Pragma("unroll") \
    for (int q_ = 0; q_ < 4; q_++) { \
        float4 v_ = av[q_]; \
        unsigned h0_ = (__float_as_uint(v_.x) + 0x8000u) & 0xFFFF0000u; \
        unsigned h1_ = (__float_as_uint(v_.y) + 0x8000u) & 0xFFFF0000u; \
        unsigned h2_ = (__float_as_uint(v_.z) + 0x8000u) & 0xFFFF0000u; \
        unsigned h3_ = (__float_as_uint(v_.w) + 0x8000u) & 0xFFFF0000u; \
        *(unsigned*)(dh_ + q_ * 4)     = (h0_ >> 16) | h1_; \
        *(unsigned*)(dh_ + q_ * 4 + 2) = (h2_ >> 16) | h3_; \
        unsigned l01_ = (unsigned)__bfloat16_as_ushort(__float2bfloat16_rn(v_.x - __uint_as_float(h0_))) \
            | ((unsigned)__bfloat16_as_ushort(__float2bfloat16_rn(v_.y - __uint_as_float(h1_))) << 16); \
        unsigned l23_ = (unsigned)__bfloat16_as_ushort(__float2bfloat16_rn(v_.z - __uint_as_float(h2_))) \
            | ((unsigned)__bfloat16_as_ushort(__float2bfloat16_rn(v_.w - __uint_as_float(h3_))) << 16); \
        *(unsigned*)(dl_ + q_ * 4)     = l01_; \
        *(unsigned*)(dl_ + q_ * 4 + 2) = l23_; \
    } \
} while (0)

#define LDB(buf, k0) do { \
    unsigned dh0_ = bHiB + ((buf) * 4352 + bi0r * 136 + bi0c) * 2; \
    unsigned dl0_ = bLoB + ((buf) * 4352 + bi0r * 136 + bi0c) * 2; \
    CPA16(dh0_, &Bh[(size_t)((k0) + bi0r) * ldb + c0 + bi0c]); \
    CPA16(dl0_, &Bl[(size_t)((k0) + bi0r) * ldb + c0 + bi0c]); \
    unsigned dh1_ = bHiB + ((buf) * 4352 + bi1r * 136 + bi1c) * 2; \
    unsigned dl1_ = bLoB + ((buf) * 4352 + bi1r * 136 + bi1c) * 2; \
    CPA16(dh1_, &Bh[(size_t)((k0) + bi1r) * ldb + c0 + bi1c]); \
    CPA16(dl1_, &Bl[(size_t)((k0) + bi1r) * ldb + c0 + bi1c]); \
    asm volatile("cp.async.commit_group;"); \
} while (0)

    // prologue: tile 0
    LOADA(kOff);
    STOREA(0);
    LDB(0, kOff);
    asm volatile("cp.async.wait_group 0;");
    __syncthreads();

    for (int t = 0; t < nt; t++) {
        const int cur = t & 1, nxt = cur ^ 1;
        const bool more = (t + 1 < nt);
        if (more) {
            LDB(nxt, kOff + (t + 1) * 32);
            LOADA(kOff + (t + 1) * 32);
        }
        mma_tile(aHiB + cur * 10240 + aOff, aLoB + cur * 10240 + aOff,
                 bHiB + cur * 8704 + bOff, bLoB + cur * 8704 + bOff, c);
        if (more) {
            STOREA(nxt);
            asm volatile("cp.async.wait_group 0;");
        }
        __syncthreads();
    }

    float* Cp = C + (size_t)blockIdx.z * partStride;
    int gq = lane >> 2, t4 = lane & 3;
#pragma unroll
    for (int mf = 0; mf < 4; mf++)
#pragma unroll
        for (int nf = 0; nf < 4; nf++) {
            int row = m0 + wm * 64 + mf * 16 + gq;
            int col = c0 + wn * 32 + nf * 8 + t4 * 2;
            *(float2*)&Cp[(size_t)row * ldc + col] = make_float2(c[mf][nf][0], c[mf][nf][1]);
            *(float2*)&Cp[(size_t)(row + 8) * ldc + col] = make_float2(c[mf][nf][2], c[mf][nf][3]);
        }
#undef LOADA
#undef STOREA
#undef LDB
}

// ---- z0 reduce + activations ----
__global__ void k_z0act(const float* __restrict__ P, float* __restrict__ s, float* __restrict__ g)
{
    int idx = blockIdx.x * blockDim.x + threadIdx.x;
    if (idx >= NN * 128) return;
    int n = idx >> 7, w = idx & 127;
    const size_t S = (size_t)NN * 256;
    size_t base = (size_t)n * 256;
    float za = (P[base + w] + P[S + base + w] + P[2 * S + base + w] + P[3 * S + base + w]) * INV_TP;
    float zb = (P[base + 128 + w] + P[S + base + 128 + w] + P[2 * S + base + 128 + w] + P[3 * S + base + 128 + w]) * INV_TP;
    s[idx] = za / (1.0f + __expf(-za));
    g[idx] = 1.0f / (1.0f + __expf(-zb));
}

// ---- z1 + gate ----
__global__ void k_z1v(const float* __restrict__ ta, const float* __restrict__ tb,
                      const float* __restrict__ hp1, const float* __restrict__ up1,
                      const float* __restrict__ gg, float* __restrict__ vmat)
{
    int n = blockIdx.x, w = threadIdx.x;
    __shared__ float u1s[192], h1s[384];
    for (int i = w; i < 192; i += 128) u1s[i] = up1[(size_t)n * 192 + i];
    for (int i = w; i < 384; i += 128) h1s[i] = hp1[(size_t)n * 384 + i];
    __syncthreads();
    float a0 = 0.f, a1 = 0.f, a2 = 0.f;
    const float* tap = ta + (size_t)n * 8192 + w;
    for (int v = 0; v < 64; v++) {
        float t = tap[v * 128];
        a0 += t * u1s[v * 3]; a1 += t * u1s[v * 3 + 1]; a2 += t * u1s[v * 3 + 2];
    }
    const float* tbp = tb + (size_t)n * 16384 + w;
    for (int u = 0; u < 128; u++) {
        float t = tbp[u * 128];
        a0 += t * h1s[u * 3]; a1 += t * h1s[u * 3 + 1]; a2 += t * h1s[u * 3 + 2];
    }
    float gv = gg[(size_t)n * 128 + w];
    vmat[(size_t)n * 384 + w * 3 + 0] = a0 * INV_TP * gv;
    vmat[(size_t)n * 384 + w * 3 + 1] = a1 * INV_TP * gv;
    vmat[(size_t)n * 384 + w * 3 + 2] = a2 * INV_TP * gv;
}

// ---- y0 ----
__global__ void k_y0(const float* __restrict__ s, const float* __restrict__ nfh,
                     const int* __restrict__ sp, const float* __restrict__ Wp0,
                     const float* __restrict__ bp0, const float* __restrict__ Wsc0,
                     float* __restrict__ y0)
{
    int nb = blockIdx.x * 4, w = threadIdx.x;
    __shared__ float ss[4][128], h0s[4][128];
    __shared__ int sps[4];
    for (int i = w; i < 512; i += 128) {
        int p = i >> 7, c = i & 127;
        ss[p][c] = s[(size_t)(nb + p) * 128 + c];
        h0s[p][c] = nfh[(size_t)(nb + p) * 512 + c];
    }
    if (w < 4) sps[w] = sp[nb + w];
    __syncthreads();
    float a[4] = {}, b[4] = {};
    for (int u = 0; u < 128; u++) {
        float wp = Wp0[u * 128 + w];
#pragma unroll
        for (int p = 0; p < 4; p++) a[p] += ss[p][u] * wp;
#pragma unroll
        for (int p = 0; p < 4; p++) b[p] += h0s[p][u] * Wsc0[u * 1280 + sps[p] * 128 + w];
    }
    float bp = bp0[w];
#pragma unroll
    for (int p = 0; p < 4; p++)
        y0[(size_t)(nb + p) * 128 + w] = a[p] * INV_H + bp + b[p] * INV_SC;
}

// ---- y1 ----
__global__ void k_y1(const float* __restrict__ vmat, const float* __restrict__ nfh,
                     const int* __restrict__ sp, const float* __restrict__ Wp1,
                     const float* __restrict__ Wsc1, float* __restrict__ y1)
{
    int nb = blockIdx.x * 2, w = threadIdx.x;
    __shared__ float vs[2][384], h1s[2][384];
    __shared__ int sps[2];
    for (int i = w; i < 768; i += 128) {
        int p = i / 384, c = i % 384;
        vs[p][c] = vmat[(size_t)(nb + p) * 384 + c];
        h1s[p][c] = nfh[(size_t)(nb + p) * 512 + 128 + c];
    }
    if (w < 2) sps[w] = sp[nb + w];
    __syncthreads();
    float a[2][3] = {}, b[2][3] = {};
    for (int u = 0; u < 128; u++) {
        float wp = Wp1[u * 128 + w];
#pragma unroll
        for (int p = 0; p < 2; p++) {
            a[p][0] += vs[p][u * 3] * wp;
            a[p][1] += vs[p][u * 3 + 1] * wp;
            a[p][2] += vs[p][u * 3 + 2] * wp;
        }
#pragma unroll
        for (int p = 0; p < 2; p++) {
            float wsc = Wsc1[u * 1280 + sps[p] * 128 + w];
            b[p][0] += h1s[p][u * 3] * wsc;
            b[p][1] += h1s[p][u * 3 + 1] * wsc;
            b[p][2] += h1s[p][u * 3 + 2] * wsc;
        }
    }
#pragma unroll
    for (int p = 0; p < 2; p++)
#pragma unroll
        for (int i = 0; i < 3; i++)
            y1[(size_t)(nb + p) * 384 + w * 3 + i] = a[p][i] * INV_H + b[p][i] * INV_SC;
}

// ---- deterministic group stats ----
__device__ __forceinline__ int lowerBound(const int* b, int n, int val)
{
    int lo = 0, hi = n;
    while (lo < hi) { int mid = (lo + hi) >> 1; if (b[mid] < val) lo = mid + 1; else hi = mid; }
    return lo;
}

__global__ void k_stats(const float* __restrict__ y0, const float* __restrict__ y1,
                        const int* __restrict__ batch,
                        float* __restrict__ mean0, float* __restrict__ rs0, float* __restrict__ rs1)
{
    int g = blockIdx.x, tid = threadIdx.x;
    int lo = lowerBound(batch, NN, g);
    int hi = lowerBound(batch, NN, g + 1);
    int cntI = hi - lo;
    float cnt = cntI < 1 ? 1.0f : (float)cntI;
    double s0 = 0.0, q0 = 0.0, q1 = 0.0;
    for (int j = tid; j < cntI * 128; j += 256) {
        float v = y0[(size_t)lo * 128 + j];
        s0 += v; q0 += (double)v * v;
    }
    for (int j = tid; j < cntI * 384; j += 256) {
        float v = y1[(size_t)lo * 384 + j];
        q1 += (double)v * v;
    }
    __shared__ double r0[256], r1[256], r2[256];
    r0[tid] = s0; r1[tid] = q0; r2[tid] = q1;
    __syncthreads();
    for (int off = 128; off > 0; off >>= 1) {
        if (tid < off) { r0[tid] += r0[tid + off]; r1[tid] += r1[tid + off]; r2[tid] += r2[tid + off]; }
        __syncthreads();
    }
    if (tid == 0) {
        double m = r0[0] / ((double)cnt * 128.0);
        double v0 = r1[0] / ((double)cnt * 128.0) - m * m;
        if (v0 < 0.0) v0 = 0.0;
        double v1 = r2[0] / ((double)cnt * 384.0);
        mean0[g] = (float)m;
        rs0[g] = 1.0f / (sqrtf((float)v0) + EPSF);
        rs1[g] = 1.0f / (sqrtf((float)v1) + EPSF);
    }
}

// ---- final output ----
__global__ void k_out(const float* __restrict__ nfh, const int* __restrict__ batch,
                      const float* __restrict__ y0, const float* __restrict__ y1,
                      const float* __restrict__ mean0, const float* __restrict__ rs0,
                      const float* __restrict__ rs1,
                      const float* __restrict__ Ws0, const float* __restrict__ bs0,
                      const float* __restrict__ Ws1,
                      const float* __restrict__ lnw0, const float* __restrict__ lnb0,
                      const float* __restrict__ lnw1, float* __restrict__ out)
{
    int nb = blockIdx.x * 2, w = threadIdx.x;
    __shared__ float h0s[2][128], h1s[2][384];
    for (int i = w; i < 1024; i += 128) {
        int p = i >> 9, c = i & 511;
        float val = nfh[(size_t)(nb + p) * 512 + c];
        if (c < 128) h0s[p][c] = val; else h1s[p][c - 128] = val;
    }
    __syncthreads();
    float o0[2] = {}, o1[2][3] = {};
    for (int u = 0; u < 128; u++) {
        float w0 = Ws0[u * 128 + w], w1 = Ws1[u * 128 + w];
#pragma unroll
        for (int p = 0; p < 2; p++) {
            o0[p] += h0s[p][u] * w0;
            o1[p][0] += h1s[p][u * 3] * w1;
            o1[p][1] += h1s[p][u * 3 + 1] * w1;
            o1[p][2] += h1s[p][u * 3 + 2] * w1;
        }
    }
    float lw0 = lnw0[w], lb0 = lnb0[w], lw1 = lnw1[w], bsw = bs0[w];
#pragma unroll
    for (int p = 0; p < 2; p++) {
        int n = nb + p, b = batch[n];
        float m = mean0[b], r0v = rs0[b], r1v = rs1[b];
        out[(size_t)n * 512 + w] =
            (y0[(size_t)n * 128 + w] - m) * r0v * lw0 + lb0 + o0[p] * INV_H + bsw;
#pragma unroll
        for (int i = 0; i < 3; i++)
            out[(size_t)n * 512 + 128 + w * 3 + i] =
                y1[(size_t)n * 384 + w * 3 + i] * r1v * lw1 + o1[p][i] * INV_H;
    }
}

// ---- host launcher ----
static void* sym(const void* s) { void* p = nullptr; cudaGetSymbolAddress(&p, s); return p; }

extern "C" void kernel_launch(void* const* d_in, const int* in_sizes, int n_in,
                              void* d_out, int out_size)
{
    const float* nfh  = (const float*)d_in[0];
    const float* nfu  = (const float*)d_in[1];
    const float* oneh = (const float*)d_in[2];
    const int* batch  = (const int*)d_in[3];
    const float* Wh0  = (const float*)d_in[4];
    const float* Wh1  = (const float*)d_in[5];
    const float* Wu0  = (const float*)d_in[6];
    const float* Wu1  = (const float*)d_in[7];
    const float* Wt00 = (const float*)d_in[8];
    const float* Wt11 = (const float*)d_in[9];
    const float* Wt01 = (const float*)d_in[10];
    const float* Wt10 = (const float*)d_in[11];
    const float* Wp0  = (const float*)d_in[12];
    const float* bp0  = (const float*)d_in[13];
    const float* Wp1  = (const float*)d_in[14];
    const float* Wsc0 = (const float*)d_in[15];
    const float* Wsc1 = (const float*)d_in[16];
    const float* lnw0 = (const float*)d_in[17];
    const float* lnb0 = (const float*)d_in[18];
    const float* lnw1 = (const float*)d_in[19];
    const float* Ws0  = (const float*)d_in[20];
    const float* bs0  = (const float*)d_in[21];
    const float* Ws1  = (const float*)d_in[22];
    float* out = (float*)d_out;

    float* hp0  = (float*)sym(g_hp0);
    float* hp1  = (float*)sym(g_hp1);
    float* up0  = (float*)sym(g_up0);
    float* up1  = (float*)sym(g_up1);
    float* Amat = (float*)sym(g_A);
    unsigned short* B0h = (unsigned short*)sym(g_B0h);
    unsigned short* B0l = (unsigned short*)sym(g_B0l);
    unsigned short* TAh = (unsigned short*)sym(g_TAh);
    unsigned short* TAl = (unsigned short*)sym(g_TAl);
    unsigned short* TBh = (unsigned short*)sym(g_TBh);
    unsigned short* TBl = (unsigned short*)sym(g_TBl);
    float* z0p  = (float*)sym(g_z0p);
    float* sbuf = (float*)sym(g_s);
    float* gbuf = (float*)sym(g_g);
    float* tab  = (float*)sym(g_ta);
    float* tbb  = (float*)sym(g_tb);
    float* vmat = (float*)sym(g_vmat);
    float* y0b  = (float*)sym(g_y0);
    float* y1b  = (float*)sym(g_y1);
    int*   spb  = (int*)sym(g_spi);
    float* mean0 = (float*)sym(g_mean0);
    float* rs0  = (float*)sym(g_rs0);
    float* rs1  = (float*)sym(g_rs1);

    cudaFuncSetAttribute(k_mma, cudaFuncAttributeMaxDynamicSharedMemorySize, SMEM_MMA_BYTES);

    k_prep<<<24576, 256>>>(Wt00, Wt11, Wt01, Wt10);
    k_sp<<<16, 256>>>(oneh, spb);
    k_proj_h<<<NN / 4, 128>>>(nfh, Wh0, Wh1, hp0, hp1);
    k_proj_u<<<NN / 4, 64>>>(nfu, Wu0, Wu1, up0, up1);
    k_xy<<<NN, 256>>>(hp0, up0, hp1, up1, Amat);
    {   // z0: (4096x16384)@(16384x256), split-K=4
        dim3 grid(32, 2, 4);
        k_mma<<<grid, 256, SMEM_MMA_BYTES>>>(Amat, 16384, B0h, B0l, 256,
                                             z0p, 256, 16384, (size_t)NN * 256);
    }
    k_z0act<<<(NN * 128 + 255) / 256, 256>>>(z0p, sbuf, gbuf);
    {   // ta: (4096x128)@(128x8192)
        dim3 grid(32, 64, 1);
        k_mma<<<grid, 256, SMEM_MMA_BYTES>>>(hp0, 128, TAh, TAl, 8192,
                                             tab, 8192, 128, 0);
    }
    {   // tb: (4096x64)@(64x16384)
        dim3 grid(32, 128, 1);
        k_mma<<<grid, 256, SMEM_MMA_BYTES>>>(up0, 64, TBh, TBl, 16384,
                                             tbb, 16384, 64, 0);
    }
    k_z1v<<<NN, 128>>>(tab, tbb, hp1, up1, gbuf, vmat);
    k_y0<<<NN / 4, 128>>>(sbuf, nfh, spb, Wp0, bp0, Wsc0, y0b);
    k_y1<<<NN / 2, 128>>>(vmat, nfh, spb, Wp1, Wsc1, y1b);
    k_stats<<<NG, 256>>>(y0b, y1b, batch, mean0, rs0, rs1);
    k_out<<<NN / 2, 128>>>(nfh, batch, y0b, y1b, mean0, rs0, rs1,
                           Ws0, bs0, Ws1, lnw0, lnb0, lnw1, out);
}

// round 13
// speedup vs baseline: 1.6191x; 1.1230x over previous
#include <cuda_runtime.h>
#include <cuda_fp16.h>
#include <stdint.h>
#include <math.h>

#define NN   4096
#define NG   64
#define NSP  10
#define EPSF 1e-5f
#define INV_H  0.08838834764831845f
#define INV_U  0.125f
#define INV_TP 0.0078125f
#define INV_SC 0.02795084971874737f
#define ISQRT3 0.57735026918962576f

// ---- static scratch ----
static __device__ float g_hp0[NN * 128];
static __device__ float g_hp1[NN * 384];
static __device__ float g_up0[NN * 64];
static __device__ float g_up1[NN * 192];
static __device__ float g_A[(size_t)NN * 16384];
static __device__ unsigned short g_B0[16384 * 256];
static __device__ unsigned short g_TA[128 * 8192];
static __device__ unsigned short g_TB[64 * 16384];
static __device__ float g_z0p[(size_t)4 * NN * 256];
static __device__ float g_s[NN * 128];
static __device__ float g_g[NN * 128];
static __device__ float g_ta[(size_t)NN * 8192];
static __device__ float g_tb[(size_t)NN * 16384];
static __device__ float g_vmat[NN * 384];
static __device__ float g_y0[NN * 128];
static __device__ float g_y1[NN * 384];
static __device__ int   g_spi[NN];
static __device__ float g_mean0[NG], g_rs0[NG], g_rs1[NG];

// ---- prep: round B matrices to fp16 ----
__global__ void k_prep(const float* __restrict__ Wt00, const float* __restrict__ Wt11,
                       const float* __restrict__ Wt01, const float* __restrict__ Wt10)
{
    const int S0 = 16384 * 256, S1 = S0 + 128 * 8192, S2 = S1 + 64 * 16384;
    int idx = blockIdx.x * blockDim.x + threadIdx.x;
    if (idx < S0) {
        int k = idx >> 8;
        float w = (k < 8192) ? Wt00[idx] : Wt11[idx - 2097152] * ISQRT3;
        g_B0[idx] = __half_as_ushort(__float2half_rn(w));
    } else if (idx < S1) {
        int j = idx - S0;
        g_TA[j] = __half_as_ushort(__float2half_rn(Wt01[j]));
    } else if (idx < S2) {
        int j = idx - S1;
        int v = j >> 14, u = (j >> 7) & 127, w = j & 127;
        g_TB[j] = __half_as_ushort(__float2half_rn(Wt10[(u * 64 + v) * 128 + w]));
    }
}

__global__ void k_sp(const float* __restrict__ onehot, int* __restrict__ sp)
{
    int n = blockIdx.x * blockDim.x + threadIdx.x;
    if (n >= NN) return;
    const float* r = onehot + (size_t)n * NSP;
    int best = 0; float bv = r[0];
#pragma unroll
    for (int i = 1; i < NSP; i++) if (r[i] > bv) { bv = r[i]; best = i; }
    sp[n] = best;
}

// ---- projections ----
__global__ void k_proj_h(const float* __restrict__ nfh,
                         const float* __restrict__ Wh0, const float* __restrict__ Wh1,
                         float* __restrict__ hp0, float* __restrict__ hp1)
{
    int nb = blockIdx.x * 4, v = threadIdx.x;
    __shared__ float h0s[4][128], h1s[4][384];
    for (int i = v; i < 2048; i += 128) {
        int p = i >> 9, c = i & 511;
        float val = nfh[(size_t)(nb + p) * 512 + c];
        if (c < 128) h0s[p][c] = val; else h1s[p][c - 128] = val;
    }
    __syncthreads();
    float a0[4] = {}, a1[4][3] = {};
    for (int u = 0; u < 128; u++) {
        float w0 = Wh0[u * 128 + v], w1 = Wh1[u * 128 + v];
#pragma unroll
        for (int p = 0; p < 4; p++) {
            a0[p] += h0s[p][u] * w0;
            a1[p][0] += h1s[p][u * 3 + 0] * w1;
            a1[p][1] += h1s[p][u * 3 + 1] * w1;
            a1[p][2] += h1s[p][u * 3 + 2] * w1;
        }
    }
#pragma unroll
    for (int p = 0; p < 4; p++) {
        hp0[(size_t)(nb + p) * 128 + v] = a0[p] * INV_H;
#pragma unroll
        for (int i = 0; i < 3; i++)
            hp1[(size_t)(nb + p) * 384 + v * 3 + i] = a1[p][i] * INV_H;
    }
}

__global__ void k_proj_u(const float* __restrict__ nfu,
                         const float* __restrict__ Wu0, const float* __restrict__ Wu1,
                         float* __restrict__ up0, float* __restrict__ up1)
{
    int nb = blockIdx.x * 4, v = threadIdx.x;
    __shared__ float u0s[4][64], u1s[4][192];
    for (int i = v; i < 1024; i += 64) {
        int p = i >> 8, c = i & 255;
        float val = nfu[(size_t)(nb + p) * 256 + c];
        if (c < 64) u0s[p][c] = val; else u1s[p][c - 64] = val;
    }
    __syncthreads();
    float a0[4] = {}, a1[4][3] = {};
    for (int u = 0; u < 64; u++) {
        float w0 = Wu0[u * 64 + v], w1 = Wu1[u * 64 + v];
#pragma unroll
        for (int p = 0; p < 4; p++) {
            a0[p] += u0s[p][u] * w0;
            a1[p][0] += u1s[p][u * 3 + 0] * w1;
            a1[p][1] += u1s[p][u * 3 + 1] * w1;
            a1[p][2] += u1s[p][u * 3 + 2] * w1;
        }
    }
#pragma unroll
    for (int p = 0; p < 4; p++) {
        up0[(size_t)(nb + p) * 64 + v] = a0[p] * INV_U;
#pragma unroll
        for (int i = 0; i < 3; i++)
            up1[(size_t)(nb + p) * 192 + v * 3 + i] = a1[p][i] * INV_U;
    }
}

// ---- outer products -> A ----
__global__ void k_xy(const float* __restrict__ hp0, const float* __restrict__ up0,
                     const float* __restrict__ hp1, const float* __restrict__ up1,
                     float* __restrict__ A)
{
    int n = blockIdx.x, tid = threadIdx.x;
    __shared__ float h0s[128], u0s[64], h1s[384], u1s[192];
    if (tid < 128) h0s[tid] = hp0[(size_t)n * 128 + tid];
    else if (tid < 192) u0s[tid - 128] = up0[(size_t)n * 64 + tid - 128];
    for (int i = tid; i < 384; i += 256) h1s[i] = hp1[(size_t)n * 384 + i];
    if (tid < 192) u1s[tid] = up1[(size_t)n * 192 + tid];
    __syncthreads();
    float* Ar = A + (size_t)n * 16384;
    for (int c = tid; c < 8192; c += 256) {
        int u = c >> 6, v = c & 63;
        Ar[c] = h0s[u] * u0s[v];
        Ar[c + 8192] = h1s[u * 3] * u1s[v * 3] + h1s[u * 3 + 1] * u1s[v * 3 + 1]
                     + h1s[u * 3 + 2] * u1s[v * 3 + 2];
    }
}

// ---- pipelined fp16 2-term split HMMA GEMM, 128x128x32 tiles, double-buffered ----
#define LDSM4(R, addr) asm volatile( \
    "ldmatrix.sync.aligned.m8n8.x4.shared.b16 {%0,%1,%2,%3}, [%4];" \
    : "=r"((R)[0]), "=r"((R)[1]), "=r"((R)[2]), "=r"((R)[3]) : "r"(addr))
#define LDSM4T(R0,R1,R2,R3, addr) asm volatile( \
    "ldmatrix.sync.aligned.m8n8.x4.trans.shared.b16 {%0,%1,%2,%3}, [%4];" \
    : "=r"(R0), "=r"(R1), "=r"(R2), "=r"(R3) : "r"(addr))
#define MMAH(Cv, Av, Bv) asm volatile( \
    "mma.sync.aligned.m16n8k16.row.col.f32.f16.f16.f32 " \
    "{%0,%1,%2,%3},{%4,%5,%6,%7},{%8,%9},{%0,%1,%2,%3};" \
    : "+f"((Cv)[0]), "+f"((Cv)[1]), "+f"((Cv)[2]), "+f"((Cv)[3]) \
    : "r"((Av)[0]), "r"((Av)[1]), "r"((Av)[2]), "r"((Av)[3]), "r"((Bv)[0]), "r"((Bv)[1]))
#define CPA16(dst, src) asm volatile( \
    "cp.async.cg.shared.global [%0], [%1], 16;" :: "r"(dst), "l"(src))

__device__ __forceinline__ void mma_tile(unsigned aHi, unsigned aLo,
                                         unsigned bA, float c[4][4][4])
{
#pragma unroll
    for (int kf = 0; kf < 2; kf++) {
        unsigned Af[4][4], Bf[4][2];
#pragma unroll
        for (int nq = 0; nq < 2; nq++) {
            unsigned r0, r1, r2, r3;
            LDSM4T(r0, r1, r2, r3, bA + kf * 4352 + nq * 32);
            Bf[2 * nq][0] = r0; Bf[2 * nq][1] = r1;
            Bf[2 * nq + 1][0] = r2; Bf[2 * nq + 1][1] = r3;
        }
#pragma unroll
        for (int mf = 0; mf < 4; mf++) LDSM4(Af[mf], aHi + mf * 1280 + kf * 32);
#pragma unroll
        for (int mf = 0; mf < 4; mf++)
#pragma unroll
            for (int nf = 0; nf < 4; nf++) MMAH(c[mf][nf], Af[mf], Bf[nf]);
#pragma unroll
        for (int mf = 0; mf < 4; mf++) LDSM4(Af[mf], aLo + mf * 1280 + kf * 32);
#pragma unroll
        for (int mf = 0; mf < 4; mf++)
#pragma unroll
            for (int nf = 0; nf < 4; nf++) MMAH(c[mf][nf], Af[mf], Bf[nf]);
    }
}

// smem halfs: sAh[2][5120] | sAl[2][5120] | sB[2][4352]
#define SMEM_MMA_BYTES ((2 * 5120 + 2 * 5120 + 2 * 4352) * 2)

__global__ __launch_bounds__(256, 2)
void k_mma(const float* __restrict__ A, int lda,
           const unsigned short* __restrict__ B, int ldb,
           float* __restrict__ C, int ldc, int Ktot, size_t partStride)
{
    extern __shared__ __align__(16) unsigned short sm[];
    unsigned short* sAh = sm;            // 2 x 5120
    unsigned short* sAl = sm + 10240;    // 2 x 5120
    unsigned short* sB  = sm + 20480;    // 2 x 4352
    const int kLen = Ktot / gridDim.z;
    const int kOff = blockIdx.z * kLen;
    const int nt = kLen >> 5;
    const int m0 = blockIdx.x * 128, c0 = blockIdx.y * 128;
    const int tid = threadIdx.x, lane = tid & 31, wid = tid >> 5;
    const int wm = wid & 1, wn = wid >> 1;
    const int ar = tid >> 1, ac = (tid & 1) << 4;

    const unsigned aHiB = (unsigned)__cvta_generic_to_shared(sAh);
    const unsigned aLoB = (unsigned)__cvta_generic_to_shared(sAl);
    const unsigned bB   = (unsigned)__cvta_generic_to_shared(sB);
    const unsigned aOff = (unsigned)(((wm * 64 + (lane & 15)) * 40 + (lane >> 4) * 8) * 2);
    const unsigned bOff = (unsigned)(((lane & 15) * 136 + wn * 32 + (lane >> 4) * 8) * 2);
    const int bi0r = tid >> 4, bi0c = (tid & 15) << 3;
    const int bi1r = (tid + 256) >> 4, bi1c = ((tid + 256) & 15) << 3;

    float c[4][4][4];
#pragma unroll
    for (int a = 0; a < 4; a++)
#pragma unroll
        for (int b = 0; b < 4; b++)
#pragma unroll
            for (int d = 0; d < 4; d++) c[a][b][d] = 0.f;

    float4 av[4];

#define LOADA(k0) do { \
    const float* ap_ = &A[(size_t)(m0 + ar) * lda + (k0) + ac]; \
    av[0] = *(const float4*)(ap_); \
    av[1] = *(const float4*)(ap_ + 4); \
    av[2] = *(const float4*)(ap_ + 8); \
    av[3] = *(const float4*)(ap_ + 12); \
} while (0)

#define STOREA(buf) do { \
    unsigned short* dh_ = sAh + (buf) * 5120 + ar * 40 + ac; \
    unsigned short* dl_ = sAl + (buf) * 5120 + ar * 40 + ac; \
    _Pragma("unroll") \
    for (int q_ = 0; q_ < 4; q_++) { \
        float4 v_ = av[q_]; \
        __half2 hA_ = __floats2half2_rn(v_.x, v_.y); \
        __half2 hB_ = __floats2half2_rn(v_.z, v_.w); \
        float2 fA_ = __half22float2(hA_), fB_ = __half22float2(hB_); \
        __half2 lA_ = __floats2half2_rn(v_.x - fA_.x, v_.y - fA_.y); \
        __half2 lB_ = __floats2half2_rn(v_.z - fB_.x, v_.w - fB_.y); \
        *(unsigned*)(dh_ + q_ * 4)     = *(unsigned*)&hA_; \
        *(unsigned*)(dh_ + q_ * 4 + 2) = *(unsigned*)&hB_; \
        *(unsigned*)(dl_ + q_ * 4)     = *(unsigned*)&lA_; \
        *(unsigned*)(dl_ + q_ * 4 + 2) = *(unsigned*)&lB_; \
    } \
} while (0)

#define LDB(buf, k0) do { \
    unsigned d0_ = bB + ((buf) * 4352 + bi0r * 136 + bi0c) * 2; \
    CPA16(d0_, &B[(size_t)((k0) + bi0r) * ldb + c0 + bi0c]); \
    unsigned d1_ = bB + ((buf) * 4352 + bi1r * 136 + bi1c) * 2; \
    CPA16(d1_, &B[(size_t)((k0) + bi1r) * ldb + c0 + bi1c]); \
    asm volatile("cp.async.commit_group;"); \
} while (0)

    // prologue: tile 0
    LOADA(kOff);
    STOREA(0);
    LDB(0, kOff);
    asm volatile("cp.async.wait_group 0;");
    __syncthreads();

    for (int t = 0; t < nt; t++) {
        const int cur = t & 1, nxt = cur ^ 1;
        const bool more = (t + 1 < nt);
        if (more) {
            LDB(nxt, kOff + (t + 1) * 32);
            LOADA(kOff + (t + 1) * 32);
        }
        mma_tile(aHiB + cur * 10240 + aOff, aLoB + cur * 10240 + aOff,
                 bB + cur * 8704 + bOff, c);
        if (more) {
            STOREA(nxt);
            asm volatile("cp.async.wait_group 0;");
        }
        __syncthreads();
    }

    float* Cp = C + (size_t)blockIdx.z * partStride;
    int gq = lane >> 2, t4 = lane & 3;
#pragma unroll
    for (int mf = 0; mf < 4; mf++)
#pragma unroll
        for (int nf = 0; nf < 4; nf++) {
            int row = m0 + wm * 64 + mf * 16 + gq;
            int col = c0 + wn * 32 + nf * 8 + t4 * 2;
            *(float2*)&Cp[(size_t)row * ldc + col] = make_float2(c[mf][nf][0], c[mf][nf][1]);
            *(float2*)&Cp[(size_t)(row + 8) * ldc + col] = make_float2(c[mf][nf][2], c[mf][nf][3]);
        }
#undef LOADA
#undef STOREA
#undef LDB
}

// ---- z0 reduce + activations ----
__global__ void k_z0act(const float* __restrict__ P, float* __restrict__ s, float* __restrict__ g)
{
    int idx = blockIdx.x * blockDim.x + threadIdx.x;
    if (idx >= NN * 128) return;
    int n = idx >> 7, w = idx & 127;
    const size_t S = (size_t)NN * 256;
    size_t base = (size_t)n * 256;
    float za = (P[base + w] + P[S + base + w] + P[2 * S + base + w] + P[3 * S + base + w]) * INV_TP;
    float zb = (P[base + 128 + w] + P[S + base + 128 + w] + P[2 * S + base + 128 + w] + P[3 * S + base + 128 + w]) * INV_TP;
    s[idx] = za / (1.0f + __expf(-za));
    g[idx] = 1.0f / (1.0f + __expf(-zb));
}

// ---- z1 + gate ----
__global__ void k_z1v(const float* __restrict__ ta, const float* __restrict__ tb,
                      const float* __restrict__ hp1, const float* __restrict__ up1,
                      const float* __restrict__ gg, float* __restrict__ vmat)
{
    int n = blockIdx.x, w = threadIdx.x;
    __shared__ float u1s[192], h1s[384];
    for (int i = w; i < 192; i += 128) u1s[i] = up1[(size_t)n * 192 + i];
    for (int i = w; i < 384; i += 128) h1s[i] = hp1[(size_t)n * 384 + i];
    __syncthreads();
    float a0 = 0.f, a1 = 0.f, a2 = 0.f;
    const float* tap = ta + (size_t)n * 8192 + w;
    for (int v = 0; v < 64; v++) {
        float t = tap[v * 128];
        a0 += t * u1s[v * 3]; a1 += t * u1s[v * 3 + 1]; a2 += t * u1s[v * 3 + 2];
    }
    const float* tbp = tb + (size_t)n * 16384 + w;
    for (int u = 0; u < 128; u++) {
        float t = tbp[u * 128];
        a0 += t * h1s[u * 3]; a1 += t * h1s[u * 3 + 1]; a2 += t * h1s[u * 3 + 2];
    }
    float gv = gg[(size_t)n * 128 + w];
    vmat[(size_t)n * 384 + w * 3 + 0] = a0 * INV_TP * gv;
    vmat[(size_t)n * 384 + w * 3 + 1] = a1 * INV_TP * gv;
    vmat[(size_t)n * 384 + w * 3 + 2] = a2 * INV_TP * gv;
}

// ---- y0 ----
__global__ void k_y0(const float* __restrict__ s, const float* __restrict__ nfh,
                     const int* __restrict__ sp, const float* __restrict__ Wp0,
                     const float* __restrict__ bp0, const float* __restrict__ Wsc0,
                     float* __restrict__ y0)
{
    int nb = blockIdx.x * 4, w = threadIdx.x;
    __shared__ float ss[4][128], h0s[4][128];
    __shared__ int sps[4];
    for (int i = w; i < 512; i += 128) {
        int p = i >> 7, c = i & 127;
        ss[p][c] = s[(size_t)(nb + p) * 128 + c];
        h0s[p][c] = nfh[(size_t)(nb + p) * 512 + c];
    }
    if (w < 4) sps[w] = sp[nb + w];
    __syncthreads();
    float a[4] = {}, b[4] = {};
    for (int u = 0; u < 128; u++) {
        float wp = Wp0[u * 128 + w];
#pragma unroll
        for (int p = 0; p < 4; p++) a[p] += ss[p][u] * wp;
#pragma unroll
        for (int p = 0; p < 4; p++) b[p] += h0s[p][u] * Wsc0[u * 1280 + sps[p] * 128 + w];
    }
    float bp = bp0[w];
#pragma unroll
    for (int p = 0; p < 4; p++)
        y0[(size_t)(nb + p) * 128 + w] = a[p] * INV_H + bp + b[p] * INV_SC;
}

// ---- y1 ----
__global__ void k_y1(const float* __restrict__ vmat, const float* __restrict__ nfh,
                     const int* __restrict__ sp, const float* __restrict__ Wp1,
                     const float* __restrict__ Wsc1, float* __restrict__ y1)
{
    int nb = blockIdx.x * 2, w = threadIdx.x;
    __shared__ float vs[2][384], h1s[2][384];
    __shared__ int sps[2];
    for (int i = w; i < 768; i += 128) {
        int p = i / 384, c = i % 384;
        vs[p][c] = vmat[(size_t)(nb + p) * 384 + c];
        h1s[p][c] = nfh[(size_t)(nb + p) * 512 + 128 + c];
    }
    if (w < 2) sps[w] = sp[nb + w];
    __syncthreads();
    float a[2][3] = {}, b[2][3] = {};
    for (int u = 0; u < 128; u++) {
        float wp = Wp1[u * 128 + w];
#pragma unroll
        for (int p = 0; p < 2; p++) {
            a[p][0] += vs[p][u * 3] * wp;
            a[p][1] += vs[p][u * 3 + 1] * wp;
            a[p][2] += vs[p][u * 3 + 2] * wp;
        }
#pragma unroll
        for (int p = 0; p < 2; p++) {
            float wsc = Wsc1[u * 1280 + sps[p] * 128 + w];
            b[p][0] += h1s[p][u * 3] * wsc;
            b[p][1] += h1s[p][u * 3 + 1] * wsc;
            b[p][2] += h1s[p][u * 3 + 2] * wsc;
        }
    }
#pragma unroll
    for (int p = 0; p < 2; p++)
#pragma unroll
        for (int i = 0; i < 3; i++)
            y1[(size_t)(nb + p) * 384 + w * 3 + i] = a[p][i] * INV_H + b[p][i] * INV_SC;
}

// ---- deterministic group stats ----
__device__ __forceinline__ int lowerBound(const int* b, int n, int val)
{
    int lo = 0, hi = n;
    while (lo < hi) { int mid = (lo + hi) >> 1; if (b[mid] < val) lo = mid + 1; else hi = mid; }
    return lo;
}

__global__ void k_stats(const float* __restrict__ y0, const float* __restrict__ y1,
                        const int* __restrict__ batch,
                        float* __restrict__ mean0, float* __restrict__ rs0, float* __restrict__ rs1)
{
    int g = blockIdx.x, tid = threadIdx.x;
    int lo = lowerBound(batch, NN, g);
    int hi = lowerBound(batch, NN, g + 1);
    int cntI = hi - lo;
    float cnt = cntI < 1 ? 1.0f : (float)cntI;
    double s0 = 0.0, q0 = 0.0, q1 = 0.0;
    for (int j = tid; j < cntI * 128; j += 256) {
        float v = y0[(size_t)lo * 128 + j];
        s0 += v; q0 += (double)v * v;
    }
    for (int j = tid; j < cntI * 384; j += 256) {
        float v = y1[(size_t)lo * 384 + j];
        q1 += (double)v * v;
    }
    __shared__ double r0[256], r1[256], r2[256];
    r0[tid] = s0; r1[tid] = q0; r2[tid] = q1;
    __syncthreads();
    for (int off = 128; off > 0; off >>= 1) {
        if (tid < off) { r0[tid] += r0[tid + off]; r1[tid] += r1[tid + off]; r2[tid] += r2[tid + off]; }
        __syncthreads();
    }
    if (tid == 0) {
        double m = r0[0] / ((double)cnt * 128.0);
        double v0 = r1[0] / ((double)cnt * 128.0) - m * m;
        if (v0 < 0.0) v0 = 0.0;
        double v1 = r2[0] / ((double)cnt * 384.0);
        mean0[g] = (float)m;
        rs0[g] = 1.0f / (sqrtf((float)v0) + EPSF);
        rs1[g] = 1.0f / (sqrtf((float)v1) + EPSF);
    }
}

// ---- final output ----
__global__ void k_out(const float* __restrict__ nfh, const int* __restrict__ batch,
                      const float* __restrict__ y0, const float* __restrict__ y1,
                      const float* __restrict__ mean0, const float* __restrict__ rs0,
                      const float* __restrict__ rs1,
                      const float* __restrict__ Ws0, const float* __restrict__ bs0,
                      const float* __restrict__ Ws1,
                      const float* __restrict__ lnw0, const float* __restrict__ lnb0,
                      const float* __restrict__ lnw1, float* __restrict__ out)
{
    int nb = blockIdx.x * 2, w = threadIdx.x;
    __shared__ float h0s[2][128], h1s[2][384];
    for (int i = w; i < 1024; i += 128) {
        int p = i >> 9, c = i & 511;
        float val = nfh[(size_t)(nb + p) * 512 + c];
        if (c < 128) h0s[p][c] = val; else h1s[p][c - 128] = val;
    }
    __syncthreads();
    float o0[2] = {}, o1[2][3] = {};
    for (int u = 0; u < 128; u++) {
        float w0 = Ws0[u * 128 + w], w1 = Ws1[u * 128 + w];
#pragma unroll
        for (int p = 0; p < 2; p++) {
            o0[p] += h0s[p][u] * w0;
            o1[p][0] += h1s[p][u * 3] * w1;
            o1[p][1] += h1s[p][u * 3 + 1] * w1;
            o1[p][2] += h1s[p][u * 3 + 2] * w1;
        }
    }
    float lw0 = lnw0[w], lb0 = lnb0[w], lw1 = lnw1[w], bsw = bs0[w];
#pragma unroll
    for (int p = 0; p < 2; p++) {
        int n = nb + p, b = batch[n];
        float m = mean0[b], r0v = rs0[b], r1v = rs1[b];
        out[(size_t)n * 512 + w] =
            (y0[(size_t)n * 128 + w] - m) * r0v * lw0 + lb0 + o0[p] * INV_H + bsw;
#pragma unroll
        for (int i = 0; i < 3; i++)
            out[(size_t)n * 512 + 128 + w * 3 + i] =
                y1[(size_t)n * 384 + w * 3 + i] * r1v * lw1 + o1[p][i] * INV_H;
    }
}

// ---- host launcher ----
static void* sym(const void* s) { void* p = nullptr; cudaGetSymbolAddress(&p, s); return p; }

extern "C" void kernel_launch(void* const* d_in, const int* in_sizes, int n_in,
                              void* d_out, int out_size)
{
    const float* nfh  = (const float*)d_in[0];
    const float* nfu  = (const float*)d_in[1];
    const float* oneh = (const float*)d_in[2];
    const int* batch  = (const int*)d_in[3];
    const float* Wh0  = (const float*)d_in[4];
    const float* Wh1  = (const float*)d_in[5];
    const float* Wu0  = (const float*)d_in[6];
    const float* Wu1  = (const float*)d_in[7];
    const float* Wt00 = (const float*)d_in[8];
    const float* Wt11 = (const float*)d_in[9];
    const float* Wt01 = (const float*)d_in[10];
    const float* Wt10 = (const float*)d_in[11];
    const float* Wp0  = (const float*)d_in[12];
    const float* bp0  = (const float*)d_in[13];
    const float* Wp1  = (const float*)d_in[14];
    const float* Wsc0 = (const float*)d_in[15];
    const float* Wsc1 = (const float*)d_in[16];
    const float* lnw0 = (const float*)d_in[17];
    const float* lnb0 = (const float*)d_in[18];
    const float* lnw1 = (const float*)d_in[19];
    const float* Ws0  = (const float*)d_in[20];
    const float* bs0  = (const float*)d_in[21];
    const float* Ws1  = (const float*)d_in[22];
    float* out = (float*)d_out;

    float* hp0  = (float*)sym(g_hp0);
    float* hp1  = (float*)sym(g_hp1);
    float* up0  = (float*)sym(g_up0);
    float* up1  = (float*)sym(g_up1);
    float* Amat = (float*)sym(g_A);
    unsigned short* B0 = (unsigned short*)sym(g_B0);
    unsigned short* TA = (unsigned short*)sym(g_TA);
    unsigned short* TB = (unsigned short*)sym(g_TB);
    float* z0p  = (float*)sym(g_z0p);
    float* sbuf = (float*)sym(g_s);
    float* gbuf = (float*)sym(g_g);
    float* tab  = (float*)sym(g_ta);
    float* tbb  = (float*)sym(g_tb);
    float* vmat = (float*)sym(g_vmat);
    float* y0b  = (float*)sym(g_y0);
    float* y1b  = (float*)sym(g_y1);
    int*   spb  = (int*)sym(g_spi);
    float* mean0 = (float*)sym(g_mean0);
    float* rs0  = (float*)sym(g_rs0);
    float* rs1  = (float*)sym(g_rs1);

    cudaFuncSetAttribute(k_mma, cudaFuncAttributeMaxDynamicSharedMemorySize, SMEM_MMA_BYTES);

    k_prep<<<24576, 256>>>(Wt00, Wt11, Wt01, Wt10);
    k_sp<<<16, 256>>>(oneh, spb);
    k_proj_h<<<NN / 4, 128>>>(nfh, Wh0, Wh1, hp0, hp1);
    k_proj_u<<<NN / 4, 64>>>(nfu, Wu0, Wu1, up0, up1);
    k_xy<<<NN, 256>>>(hp0, up0, hp1, up1, Amat);
    {   // z0: (4096x16384)@(16384x256), split-K=4
        dim3 grid(32, 2, 4);
        k_mma<<<grid, 256, SMEM_MMA_BYTES>>>(Amat, 16384, B0, 256,
                                             z0p, 256, 16384, (size_t)NN * 256);
    }
    k_z0act<<<(NN * 128 + 255) / 256, 256>>>(z0p, sbuf, gbuf);
    {   // ta: (4096x128)@(128x8192)
        dim3 grid(32, 64, 1);
        k_mma<<<grid, 256, SMEM_MMA_BYTES>>>(hp0, 128, TA, 8192,
                                             tab, 8192, 128, 0);
    }
    {   // tb: (4096x64)@(64x16384)
        dim3 grid(32, 128, 1);
        k_mma<<<grid, 256, SMEM_MMA_BYTES>>>(up0, 64, TB, 16384,
                                             tbb, 16384, 64, 0);
    }
    k_z1v<<<NN, 128>>>(tab, tbb, hp1, up1, gbuf, vmat);
    k_y0<<<NN / 4, 128>>>(sbuf, nfh, spb, Wp0, bp0, Wsc0, y0b);
    k_y1<<<NN / 2, 128>>>(vmat, nfh, spb, Wp1, Wsc1, y1b);
    k_stats<<<NG, 256>>>(y0b, y1b, batch, mean0, rs0, rs1);
    k_out<<<NN / 2, 128>>>(nfh, batch, y0b, y1b, mean0, rs0, rs1,
                           Ws0, bs0, Ws1, lnw0, lnb0, lnw1, out);
}

// round 16
// speedup vs baseline: 1.6667x; 1.0294x over previous
#include <cuda_runtime.h>
#include <cuda_fp16.h>
#include <stdint.h>
#include <math.h>

#define NN   4096
#define NG   64
#define NSP  10
#define EPSF 1e-5f
#define INV_H  0.08838834764831845f
#define INV_U  0.125f
#define INV_TP 0.0078125f
#define INV_SC 0.02795084971874737f
#define ISQRT3 0.57735026918962576f

// ---- static scratch ----
static __device__ float g_hp0[NN * 128];
static __device__ float g_hp1[NN * 384];
static __device__ float g_up0[NN * 64];
static __device__ float g_up1[NN * 192];
static __device__ unsigned short g_Axh[(size_t)NN * 16384];  // A fp16 hi plane
static __device__ unsigned short g_Axl[(size_t)NN * 16384];  // A fp16 lo plane
static __device__ unsigned short g_B0[16384 * 256];
static __device__ unsigned short g_TA[128 * 8192];
static __device__ unsigned short g_TB[64 * 16384];
static __device__ float g_z0p[(size_t)4 * NN * 256];
static __device__ float g_s[NN * 128];
static __device__ float g_g[NN * 128];
static __device__ float g_ta[(size_t)NN * 8192];
static __device__ float g_tb[(size_t)NN * 16384];
static __device__ float g_vmat[NN * 384];
static __device__ float g_y0[NN * 128];
static __device__ float g_y1[NN * 384];
static __device__ int   g_spi[NN];
static __device__ float g_mean0[NG], g_rs0[NG], g_rs1[NG];

// ---- prep: round B matrices to fp16 ----
__global__ void k_prep(const float* __restrict__ Wt00, const float* __restrict__ Wt11,
                       const float* __restrict__ Wt01, const float* __restrict__ Wt10)
{
    const int S0 = 16384 * 256, S1 = S0 + 128 * 8192, S2 = S1 + 64 * 16384;
    int idx = blockIdx.x * blockDim.x + threadIdx.x;
    if (idx < S0) {
        int k = idx >> 8;
        float w = (k < 8192) ? Wt00[idx] : Wt11[idx - 2097152] * ISQRT3;
        g_B0[idx] = __half_as_ushort(__float2half_rn(w));
    } else if (idx < S1) {
        int j = idx - S0;
        g_TA[j] = __half_as_ushort(__float2half_rn(Wt01[j]));
    } else if (idx < S2) {
        int j = idx - S1;
        int v = j >> 14, u = (j >> 7) & 127, w = j & 127;
        g_TB[j] = __half_as_ushort(__float2half_rn(Wt10[(u * 64 + v) * 128 + w]));
    }
}

__global__ void k_sp(const float* __restrict__ onehot, int* __restrict__ sp)
{
    int n = blockIdx.x * blockDim.x + threadIdx.x;
    if (n >= NN) return;
    const float* r = onehot + (size_t)n * NSP;
    int best = 0; float bv = r[0];
#pragma unroll
    for (int i = 1; i < NSP; i++) if (r[i] > bv) { bv = r[i]; best = i; }
    sp[n] = best;
}

// ---- projections ----
__global__ void k_proj_h(const float* __restrict__ nfh,
                         const float* __restrict__ Wh0, const float* __restrict__ Wh1,
                         float* __restrict__ hp0, float* __restrict__ hp1)
{
    int nb = blockIdx.x * 4, v = threadIdx.x;
    __shared__ float h0s[4][128], h1s[4][384];
    for (int i = v; i < 2048; i += 128) {
        int p = i >> 9, c = i & 511;
        float val = nfh[(size_t)(nb + p) * 512 + c];
        if (c < 128) h0s[p][c] = val; else h1s[p][c - 128] = val;
    }
    __syncthreads();
    float a0[4] = {}, a1[4][3] = {};
    for (int u = 0; u < 128; u++) {
        float w0 = Wh0[u * 128 + v], w1 = Wh1[u * 128 + v];
#pragma unroll
        for (int p = 0; p < 4; p++) {
            a0[p] += h0s[p][u] * w0;
            a1[p][0] += h1s[p][u * 3 + 0] * w1;
            a1[p][1] += h1s[p][u * 3 + 1] * w1;
            a1[p][2] += h1s[p][u * 3 + 2] * w1;
        }
    }
#pragma unroll
    for (int p = 0; p < 4; p++) {
        hp0[(size_t)(nb + p) * 128 + v] = a0[p] * INV_H;
#pragma unroll
        for (int i = 0; i < 3; i++)
            hp1[(size_t)(nb + p) * 384 + v * 3 + i] = a1[p][i] * INV_H;
    }
}

__global__ void k_proj_u(const float* __restrict__ nfu,
                         const float* __restrict__ Wu0, const float* __restrict__ Wu1,
                         float* __restrict__ up0, float* __restrict__ up1)
{
    int nb = blockIdx.x * 4, v = threadIdx.x;
    __shared__ float u0s[4][64], u1s[4][192];
    for (int i = v; i < 1024; i += 64) {
        int p = i >> 8, c = i & 255;
        float val = nfu[(size_t)(nb + p) * 256 + c];
        if (c < 64) u0s[p][c] = val; else u1s[p][c - 64] = val;
    }
    __syncthreads();
    float a0[4] = {}, a1[4][3] = {};
    for (int u = 0; u < 64; u++) {
        float w0 = Wu0[u * 64 + v], w1 = Wu1[u * 64 + v];
#pragma unroll
        for (int p = 0; p < 4; p++) {
            a0[p] += u0s[p][u] * w0;
            a1[p][0] += u1s[p][u * 3 + 0] * w1;
            a1[p][1] += u1s[p][u * 3 + 1] * w1;
            a1[p][2] += u1s[p][u * 3 + 2] * w1;
        }
    }
#pragma unroll
    for (int p = 0; p < 4; p++) {
        up0[(size_t)(nb + p) * 64 + v] = a0[p] * INV_U;
#pragma unroll
        for (int i = 0; i < 3; i++)
            up1[(size_t)(nb + p) * 192 + v * 3 + i] = a1[p][i] * INV_U;
    }
}

// ---- outer products -> A (pre-split fp16 hi/lo planes) ----
__global__ void k_xy(const float* __restrict__ hp0, const float* __restrict__ up0,
                     const float* __restrict__ hp1, const float* __restrict__ up1,
                     unsigned short* __restrict__ Axh, unsigned short* __restrict__ Axl)
{
    int n = blockIdx.x, tid = threadIdx.x;
    __shared__ float h0s[128], u0s[64], h1s[384], u1s[192];
    if (tid < 128) h0s[tid] = hp0[(size_t)n * 128 + tid];
    else if (tid < 192) u0s[tid - 128] = up0[(size_t)n * 64 + tid - 128];
    for (int i = tid; i < 384; i += 256) h1s[i] = hp1[(size_t)n * 384 + i];
    if (tid < 192) u1s[tid] = up1[(size_t)n * 192 + tid];
    __syncthreads();
    unsigned* Hh = (unsigned*)(Axh + (size_t)n * 16384);
    unsigned* Hl = (unsigned*)(Axl + (size_t)n * 16384);
    for (int c2 = tid; c2 < 4096; c2 += 256) {
        int c = c2 * 2;
        int u = c >> 6, v = c & 63;
        float a0 = h0s[u] * u0s[v];
        float a1 = h0s[u] * u0s[v + 1];
        __half2 h = __floats2half2_rn(a0, a1);
        float2 f = __half22float2(h);
        __half2 l = __floats2half2_rn(a0 - f.x, a1 - f.y);
        Hh[c2] = *(unsigned*)&h;
        Hl[c2] = *(unsigned*)&l;
        float b0 = h1s[u * 3] * u1s[v * 3] + h1s[u * 3 + 1] * u1s[v * 3 + 1]
                 + h1s[u * 3 + 2] * u1s[v * 3 + 2];
        float b1 = h1s[u * 3] * u1s[(v + 1) * 3] + h1s[u * 3 + 1] * u1s[(v + 1) * 3 + 1]
                 + h1s[u * 3 + 2] * u1s[(v + 1) * 3 + 2];
        __half2 hb = __floats2half2_rn(b0, b1);
        float2 fb = __half22float2(hb);
        __half2 lb = __floats2half2_rn(b0 - fb.x, b1 - fb.y);
        Hh[c2 + 4096] = *(unsigned*)&hb;
        Hl[c2 + 4096] = *(unsigned*)&lb;
    }
}

// ---- pipelined fp16 2-term split HMMA GEMM, 128x128x32 tiles, double-buffered ----
#define LDSM4(R, addr) asm volatile( \
    "ldmatrix.sync.aligned.m8n8.x4.shared.b16 {%0,%1,%2,%3}, [%4];" \
    : "=r"((R)[0]), "=r"((R)[1]), "=r"((R)[2]), "=r"((R)[3]) : "r"(addr))
#define LDSM4T(R0,R1,R2,R3, addr) asm volatile( \
    "ldmatrix.sync.aligned.m8n8.x4.trans.shared.b16 {%0,%1,%2,%3}, [%4];" \
    : "=r"(R0), "=r"(R1), "=r"(R2), "=r"(R3) : "r"(addr))
#define MMAH(Cv, Av, Bv) asm volatile( \
    "mma.sync.aligned.m16n8k16.row.col.f32.f16.f16.f32 " \
    "{%0,%1,%2,%3},{%4,%5,%6,%7},{%8,%9},{%0,%1,%2,%3};" \
    : "+f"((Cv)[0]), "+f"((Cv)[1]), "+f"((Cv)[2]), "+f"((Cv)[3]) \
    : "r"((Av)[0]), "r"((Av)[1]), "r"((Av)[2]), "r"((Av)[3]), "r"((Bv)[0]), "r"((Bv)[1]))
#define CPA16(dst, src) asm volatile( \
    "cp.async.cg.shared.global [%0], [%1], 16;" :: "r"(dst), "l"(src))

__device__ __forceinline__ void mma_tile(unsigned aHi, unsigned aLo,
                                         unsigned bA, float c[4][4][4])
{
#pragma unroll
    for (int kf = 0; kf < 2; kf++) {
        unsigned Af[4][4], Bf[4][2];
#pragma unroll
        for (int nq = 0; nq < 2; nq++) {
            unsigned r0, r1, r2, r3;
            LDSM4T(r0, r1, r2, r3, bA + kf * 4352 + nq * 32);
            Bf[2 * nq][0] = r0; Bf[2 * nq][1] = r1;
            Bf[2 * nq + 1][0] = r2; Bf[2 * nq + 1][1] = r3;
        }
#pragma unroll
        for (int mf = 0; mf < 4; mf++) LDSM4(Af[mf], aHi + mf * 1280 + kf * 32);
#pragma unroll
        for (int mf = 0; mf < 4; mf++)
#pragma unroll
            for (int nf = 0; nf < 4; nf++) MMAH(c[mf][nf], Af[mf], Bf[nf]);
#pragma unroll
        for (int mf = 0; mf < 4; mf++) LDSM4(Af[mf], aLo + mf * 1280 + kf * 32);
#pragma unroll
        for (int mf = 0; mf < 4; mf++)
#pragma unroll
            for (int nf = 0; nf < 4; nf++) MMAH(c[mf][nf], Af[mf], Bf[nf]);
    }
}

// smem halfs: sAh[2][5120] | sAl[2][5120] | sB[2][4352]
#define SMEM_MMA_BYTES ((2 * 5120 + 2 * 5120 + 2 * 4352) * 2)

// PRESPLIT=1: A given as fp16 hi/lo planes, loaded via cp.async (z0 path).
// PRESPLIT=0: fp32 A, split on the fly (ta/tb path).
template <int PRESPLIT>
__global__ __launch_bounds__(256, 2)
void k_mma(const float* __restrict__ A,
           const unsigned short* __restrict__ Aph, const unsigned short* __restrict__ Apl,
           int lda,
           const unsigned short* __restrict__ B, int ldb,
           float* __restrict__ C, int ldc, int Ktot, size_t partStride)
{
    extern __shared__ __align__(16) unsigned short sm[];
    unsigned short* sAh = sm;            // 2 x 5120
    unsigned short* sAl = sm + 10240;    // 2 x 5120
    unsigned short* sB  = sm + 20480;    // 2 x 4352
    const int kLen = Ktot / gridDim.z;
    const int kOff = blockIdx.z * kLen;
    const int nt = kLen >> 5;
    const int m0 = blockIdx.x * 128, c0 = blockIdx.y * 128;
    const int tid = threadIdx.x, lane = tid & 31, wid = tid >> 5;
    const int wm = wid & 1, wn = wid >> 1;
    const int ar = tid >> 1, ac = (tid & 1) << 4;

    const unsigned aHiB = (unsigned)__cvta_generic_to_shared(sAh);
    const unsigned aLoB = (unsigned)__cvta_generic_to_shared(sAl);
    const unsigned bB   = (unsigned)__cvta_generic_to_shared(sB);
    const unsigned aOff = (unsigned)(((wm * 64 + (lane & 15)) * 40 + (lane >> 4) * 8) * 2);
    const unsigned bOff = (unsigned)(((lane & 15) * 136 + wn * 32 + (lane >> 4) * 8) * 2);
    const int bi0r = tid >> 4, bi0c = (tid & 15) << 3;
    const int bi1r = (tid + 256) >> 4, bi1c = ((tid + 256) & 15) << 3;
    // A cp.async chunks (PRESPLIT): 512 16B-chunks per plane per tile, 2 per thread per plane
    const int a0r = tid >> 2, a0s = (tid & 3) << 3;
    const int a1r = (tid + 256) >> 2, a1s = ((tid + 256) & 3) << 3;

    float c[4][4][4];
#pragma unroll
    for (int a = 0; a < 4; a++)
#pragma unroll
        for (int b = 0; b < 4; b++)
#pragma unroll
            for (int d = 0; d < 4; d++) c[a][b][d] = 0.f;

    float4 av[4];

#define LOADA(k0) do { \
    const float* ap_ = &A[(size_t)(m0 + ar) * lda + (k0) + ac]; \
    av[0] = *(const float4*)(ap_); \
    av[1] = *(const float4*)(ap_ + 4); \
    av[2] = *(const float4*)(ap_ + 8); \
    av[3] = *(const float4*)(ap_ + 12); \
} while (0)

#define STOREA(buf) do { \
    unsigned short* dh_ = sAh + (buf) * 5120 + ar * 40 + ac; \
    unsigned short* dl_ = sAl + (buf) * 5120 + ar * 40 + ac; \
    _Pragma("unroll") \
    for (int q_ = 0; q_ < 4; q_++) { \
        float4 v_ = av[q_]; \
        __half2 hA_ = __floats2half2_rn(v_.x, v_.y); \
        __half2 hB_ = __floats2half2_rn(v_.z, v_.w); \
        float2 fA_ = __half22float2(hA_), fB_ = __half22float2(hB_); \
        __half2 lA_ = __floats2half2_rn(v_.x - fA_.x, v_.y - fA_.y); \
        __half2 lB_ = __floats2half2_rn(v_.z - fB_.x, v_.w - fB_.y); \
        *(unsigned*)(dh_ + q_ * 4)     = *(unsigned*)&hA_; \
        *(unsigned*)(dh_ + q_ * 4 + 2) = *(unsigned*)&hB_; \
        *(unsigned*)(dl_ + q_ * 4)     = *(unsigned*)&lA_; \
        *(unsigned*)(dl_ + q_ * 4 + 2) = *(unsigned*)&lB_; \
    } \
} while (0)

#define LDAP(buf, k0) do { \
    unsigned dh0_ = aHiB + ((buf) * 5120 + a0r * 40 + a0s) * 2; \
    unsigned dh1_ = aHiB + ((buf) * 5120 + a1r * 40 + a1s) * 2; \
    unsigned dl0_ = aLoB + ((buf) * 5120 + a0r * 40 + a0s) * 2; \
    unsigned dl1_ = aLoB + ((buf) * 5120 + a1r * 40 + a1s) * 2; \
    CPA16(dh0_, &Aph[(size_t)(m0 + a0r) * lda + (k0) + a0s]); \
    CPA16(dh1_, &Aph[(size_t)(m0 + a1r) * lda + (k0) + a1s]); \
    CPA16(dl0_, &Apl[(size_t)(m0 + a0r) * lda + (k0) + a0s]); \
    CPA16(dl1_, &Apl[(size_t)(m0 + a1r) * lda + (k0) + a1s]); \
} while (0)

#define LDB(buf, k0) do { \
    unsigned d0_ = bB + ((buf) * 4352 + bi0r * 136 + bi0c) * 2; \
    CPA16(d0_, &B[(size_t)((k0) + bi0r) * ldb + c0 + bi0c]); \
    unsigned d1_ = bB + ((buf) * 4352 + bi1r * 136 + bi1c) * 2; \
    CPA16(d1_, &B[(size_t)((k0) + bi1r) * ldb + c0 + bi1c]); \
    asm volatile("cp.async.commit_group;"); \
} while (0)

    // prologue: tile 0
    if (PRESPLIT) {
        LDAP(0, kOff);
    } else {
        LOADA(kOff);
        STOREA(0);
    }
    LDB(0, kOff);
    asm volatile("cp.async.wait_group 0;");
    __syncthreads();

    for (int t = 0; t < nt; t++) {
        const int cur = t & 1, nxt = cur ^ 1;
        const bool more = (t + 1 < nt);
        if (more) {
            if (PRESPLIT) LDAP(nxt, kOff + (t + 1) * 32);
            LDB(nxt, kOff + (t + 1) * 32);
            if (!PRESPLIT) LOADA(kOff + (t + 1) * 32);
        }
        mma_tile(aHiB + cur * 10240 + aOff, aLoB + cur * 10240 + aOff,
                 bB + cur * 8704 + bOff, c);
        if (more) {
            if (!PRESPLIT) STOREA(nxt);
            asm volatile("cp.async.wait_group 0;");
        }
        __syncthreads();
    }

    float* Cp = C + (size_t)blockIdx.z * partStride;
    int gq = lane >> 2, t4 = lane & 3;
#pragma unroll
    for (int mf = 0; mf < 4; mf++)
#pragma unroll
        for (int nf = 0; nf < 4; nf++) {
            int row = m0 + wm * 64 + mf * 16 + gq;
            int col = c0 + wn * 32 + nf * 8 + t4 * 2;
            *(float2*)&Cp[(size_t)row * ldc + col] = make_float2(c[mf][nf][0], c[mf][nf][1]);
            *(float2*)&Cp[(size_t)(row + 8) * ldc + col] = make_float2(c[mf][nf][2], c[mf][nf][3]);
        }
#undef LOADA
#undef STOREA
#undef LDAP
#undef LDB
}

// ---- z0 reduce + activations ----
__global__ void k_z0act(const float* __restrict__ P, float* __restrict__ s, float* __restrict__ g)
{
    int idx = blockIdx.x * blockDim.x + threadIdx.x;
    if (idx >= NN * 128) return;
    int n = idx >> 7, w = idx & 127;
    const size_t S = (size_t)NN * 256;
    size_t base = (size_t)n * 256;
    float za = (P[base + w] + P[S + base + w] + P[2 * S + base + w] + P[3 * S + base + w]) * INV_TP;
    float zb = (P[base + 128 + w] + P[S + base + 128 + w] + P[2 * S + base + 128 + w] + P[3 * S + base + 128 + w]) * INV_TP;
    s[idx] = za / (1.0f + __expf(-za));
    g[idx] = 1.0f / (1.0f + __expf(-zb));
}

// ---- z1 + gate ----
__global__ void k_z1v(const float* __restrict__ ta, const float* __restrict__ tb,
                      const float* __restrict__ hp1, const float* __restrict__ up1,
                      const float* __restrict__ gg, float* __restrict__ vmat)
{
    int n = blockIdx.x, w = threadIdx.x;
    __shared__ float u1s[192], h1s[384];
    for (int i = w; i < 192; i += 128) u1s[i] = up1[(size_t)n * 192 + i];
    for (int i = w; i < 384; i += 128) h1s[i] = hp1[(size_t)n * 384 + i];
    __syncthreads();
    float a0 = 0.f, a1 = 0.f, a2 = 0.f;
    const float* tap = ta + (size_t)n * 8192 + w;
    for (int v = 0; v < 64; v++) {
        float t = tap[v * 128];
        a0 += t * u1s[v * 3]; a1 += t * u1s[v * 3 + 1]; a2 += t * u1s[v * 3 + 2];
    }
    const float* tbp = tb + (size_t)n * 16384 + w;
    for (int u = 0; u < 128; u++) {
        float t = tbp[u * 128];
        a0 += t * h1s[u * 3]; a1 += t * h1s[u * 3 + 1]; a2 += t * h1s[u * 3 + 2];
    }
    float gv = gg[(size_t)n * 128 + w];
    vmat[(size_t)n * 384 + w * 3 + 0] = a0 * INV_TP * gv;
    vmat[(size_t)n * 384 + w * 3 + 1] = a1 * INV_TP * gv;
    vmat[(size_t)n * 384 + w * 3 + 2] = a2 * INV_TP * gv;
}

// ---- y0 ----
__global__ void k_y0(const float* __restrict__ s, const float* __restrict__ nfh,
                     const int* __restrict__ sp, const float* __restrict__ Wp0,
                     const float* __restrict__ bp0, const float* __restrict__ Wsc0,
                     float* __restrict__ y0)
{
    int nb = blockIdx.x * 4, w = threadIdx.x;
    __shared__ float ss[4][128], h0s[4][128];
    __shared__ int sps[4];
    for (int i = w; i < 512; i += 128) {
        int p = i >> 7, c = i & 127;
        ss[p][c] = s[(size_t)(nb + p) * 128 + c];
        h0s[p][c] = nfh[(size_t)(nb + p) * 512 + c];
    }
    if (w < 4) sps[w] = sp[nb + w];
    __syncthreads();
    float a[4] = {}, b[4] = {};
    for (int u = 0; u < 128; u++) {
        float wp = Wp0[u * 128 + w];
#pragma unroll
        for (int p = 0; p < 4; p++) a[p] += ss[p][u] * wp;
#pragma unroll
        for (int p = 0; p < 4; p++) b[p] += h0s[p][u] * Wsc0[u * 1280 + sps[p] * 128 + w];
    }
    float bp = bp0[w];
#pragma unroll
    for (int p = 0; p < 4; p++)
        y0[(size_t)(nb + p) * 128 + w] = a[p] * INV_H + bp + b[p] * INV_SC;
}

// ---- y1 ----
__global__ void k_y1(const float* __restrict__ vmat, const float* __restrict__ nfh,
                     const int* __restrict__ sp, const float* __restrict__ Wp1,
                     const float* __restrict__ Wsc1, float* __restrict__ y1)
{
    int nb = blockIdx.x * 2, w = threadIdx.x;
    __shared__ float vs[2][384], h1s[2][384];
    __shared__ int sps[2];
    for (int i = w; i < 768; i += 128) {
        int p = i / 384, c = i % 384;
        vs[p][c] = vmat[(size_t)(nb + p) * 384 + c];
        h1s[p][c] = nfh[(size_t)(nb + p) * 512 + 128 + c];
    }
    if (w < 2) sps[w] = sp[nb + w];
    __syncthreads();
    float a[2][3] = {}, b[2][3] = {};
    for (int u = 0; u < 128; u++) {
        float wp = Wp1[u * 128 + w];
#pragma unroll
        for (int p = 0; p < 2; p++) {
            a[p][0] += vs[p][u * 3] * wp;
            a[p][1] += vs[p][u * 3 + 1] * wp;
            a[p][2] += vs[p][u * 3 + 2] * wp;
        }
#pragma unroll
        for (int p = 0; p < 2; p++) {
            float wsc = Wsc1[u * 1280 + sps[p] * 128 + w];
            b[p][0] += h1s[p][u * 3] * wsc;
            b[p][1] += h1s[p][u * 3 + 1] * wsc;
            b[p][2] += h1s[p][u * 3 + 2] * wsc;
        }
    }
#pragma unroll
    for (int p = 0; p < 2; p++)
#pragma unroll
        for (int i = 0; i < 3; i++)
            y1[(size_t)(nb + p) * 384 + w * 3 + i] = a[p][i] * INV_H + b[p][i] * INV_SC;
}

// ---- deterministic group stats ----
__device__ __forceinline__ int lowerBound(const int* b, int n, int val)
{
    int lo = 0, hi = n;
    while (lo < hi) { int mid = (lo + hi) >> 1; if (b[mid] < val) lo = mid + 1; else hi = mid; }
    return lo;
}

__global__ void k_stats(const float* __restrict__ y0, const float* __restrict__ y1,
                        const int* __restrict__ batch,
                        float* __restrict__ mean0, float* __restrict__ rs0, float* __restrict__ rs1)
{
    int g = blockIdx.x, tid = threadIdx.x;
    int lo = lowerBound(batch, NN, g);
    int hi = lowerBound(batch, NN, g + 1);
    int cntI = hi - lo;
    float cnt = cntI < 1 ? 1.0f : (float)cntI;
    double s0 = 0.0, q0 = 0.0, q1 = 0.0;
    for (int j = tid; j < cntI * 128; j += 256) {
        float v = y0[(size_t)lo * 128 + j];
        s0 += v; q0 += (double)v * v;
    }
    for (int j = tid; j < cntI * 384; j += 256) {
        float v = y1[(size_t)lo * 384 + j];
        q1 += (double)v * v;
    }
    __shared__ double r0[256], r1[256], r2[256];
    r0[tid] = s0; r1[tid] = q0; r2[tid] = q1;
    __syncthreads();
    for (int off = 128; off > 0; off >>= 1) {
        if (tid < off) { r0[tid] += r0[tid + off]; r1[tid] += r1[tid + off]; r2[tid] += r2[tid + off]; }
        __syncthreads();
    }
    if (tid == 0) {
        double m = r0[0] / ((double)cnt * 128.0);
        double v0 = r1[0] / ((double)cnt * 128.0) - m * m;
        if (v0 < 0.0) v0 = 0.0;
        double v1 = r2[0] / ((double)cnt * 384.0);
        mean0[g] = (float)m;
        rs0[g] = 1.0f / (sqrtf((float)v0) + EPSF);
        rs1[g] = 1.0f / (sqrtf((float)v1) + EPSF);
    }
}

// ---- final output ----
__global__ void k_out(const float* __restrict__ nfh, const int* __restrict__ batch,
                      const float* __restrict__ y0, const float* __restrict__ y1,
                      const float* __restrict__ mean0, const float* __restrict__ rs0,
                      const float* __restrict__ rs1,
                      const float* __restrict__ Ws0, const float* __restrict__ bs0,
                      const float* __restrict__ Ws1,
                      const float* __restrict__ lnw0, const float* __restrict__ lnb0,
                      const float* __restrict__ lnw1, float* __restrict__ out)
{
    int nb = blockIdx.x * 2, w = threadIdx.x;
    __shared__ float h0s[2][128], h1s[2][384];
    for (int i = w; i < 1024; i += 128) {
        int p = i >> 9, c = i & 511;
        float val = nfh[(size_t)(nb + p) * 512 + c];
        if (c < 128) h0s[p][c] = val; else h1s[p][c - 128] = val;
    }
    __syncthreads();
    float o0[2] = {}, o1[2][3] = {};
    for (int u = 0; u < 128; u++) {
        float w0 = Ws0[u * 128 + w], w1 = Ws1[u * 128 + w];
#pragma unroll
        for (int p = 0; p < 2; p++) {
            o0[p] += h0s[p][u] * w0;
            o1[p][0] += h1s[p][u * 3] * w1;
            o1[p][1] += h1s[p][u * 3 + 1] * w1;
            o1[p][2] += h1s[p][u * 3 + 2] * w1;
        }
    }
    float lw0 = lnw0[w], lb0 = lnb0[w], lw1 = lnw1[w], bsw = bs0[w];
#pragma unroll
    for (int p = 0; p < 2; p++) {
        int n = nb + p, b = batch[n];
        float m = mean0[b], r0v = rs0[b], r1v = rs1[b];
        out[(size_t)n * 512 + w] =
            (y0[(size_t)n * 128 + w] - m) * r0v * lw0 + lb0 + o0[p] * INV_H + bsw;
#pragma unroll
        for (int i = 0; i < 3; i++)
            out[(size_t)n * 512 + 128 + w * 3 + i] =
                y1[(size_t)n * 384 + w * 3 + i] * r1v * lw1 + o1[p][i] * INV_H;
    }
}

// ---- host launcher ----
static void* sym(const void* s) { void* p = nullptr; cudaGetSymbolAddress(&p, s); return p; }

extern "C" void kernel_launch(void* const* d_in, const int* in_sizes, int n_in,
                              void* d_out, int out_size)
{
    const float* nfh  = (const float*)d_in[0];
    const float* nfu  = (const float*)d_in[1];
    const float* oneh = (const float*)d_in[2];
    const int* batch  = (const int*)d_in[3];
    const float* Wh0  = (const float*)d_in[4];
    const float* Wh1  = (const float*)d_in[5];
    const float* Wu0  = (const float*)d_in[6];
    const float* Wu1  = (const float*)d_in[7];
    const float* Wt00 = (const float*)d_in[8];
    const float* Wt11 = (const float*)d_in[9];
    const float* Wt01 = (const float*)d_in[10];
    const float* Wt10 = (const float*)d_in[11];
    const float* Wp0  = (const float*)d_in[12];
    const float* bp0  = (const float*)d_in[13];
    const float* Wp1  = (const float*)d_in[14];
    const float* Wsc0 = (const float*)d_in[15];
    const float* Wsc1 = (const float*)d_in[16];
    const float* lnw0 = (const float*)d_in[17];
    const float* lnb0 = (const float*)d_in[18];
    const float* lnw1 = (const float*)d_in[19];
    const float* Ws0  = (const float*)d_in[20];
    const float* bs0  = (const float*)d_in[21];
    const float* Ws1  = (const float*)d_in[22];
    float* out = (float*)d_out;

    float* hp0  = (float*)sym(g_hp0);
    float* hp1  = (float*)sym(g_hp1);
    float* up0  = (float*)sym(g_up0);
    float* up1  = (float*)sym(g_up1);
    unsigned short* Axh = (unsigned short*)sym(g_Axh);
    unsigned short* Axl = (unsigned short*)sym(g_Axl);
    unsigned short* B0 = (unsigned short*)sym(g_B0);
    unsigned short* TA = (unsigned short*)sym(g_TA);
    unsigned short* TB = (unsigned short*)sym(g_TB);
    float* z0p  = (float*)sym(g_z0p);
    float* sbuf = (float*)sym(g_s);
    float* gbuf = (float*)sym(g_g);
    float* tab  = (float*)sym(g_ta);
    float* tbb  = (float*)sym(g_tb);
    float* vmat = (float*)sym(g_vmat);
    float* y0b  = (float*)sym(g_y0);
    float* y1b  = (float*)sym(g_y1);
    int*   spb  = (int*)sym(g_spi);
    float* mean0 = (float*)sym(g_mean0);
    float* rs0  = (float*)sym(g_rs0);
    float* rs1  = (float*)sym(g_rs1);

    cudaFuncSetAttribute(k_mma<0>, cudaFuncAttributeMaxDynamicSharedMemorySize, SMEM_MMA_BYTES);
    cudaFuncSetAttribute(k_mma<1>, cudaFuncAttributeMaxDynamicSharedMemorySize, SMEM_MMA_BYTES);

    k_prep<<<24576, 256>>>(Wt00, Wt11, Wt01, Wt10);
    k_sp<<<16, 256>>>(oneh, spb);
    k_proj_h<<<NN / 4, 128>>>(nfh, Wh0, Wh1, hp0, hp1);
    k_proj_u<<<NN / 4, 64>>>(nfu, Wu0, Wu1, up0, up1);
    k_xy<<<NN, 256>>>(hp0, up0, hp1, up1, Axh, Axl);
    {   // z0: (4096x16384)@(16384x256), split-K=4, pre-split A via cp.async
        dim3 grid(32, 2, 4);
        k_mma<1><<<grid, 256, SMEM_MMA_BYTES>>>(nullptr, Axh, Axl, 16384, B0, 256,
                                                z0p, 256, 16384, (size_t)NN * 256);
    }
    k_z0act<<<(NN * 128 + 255) / 256, 256>>>(z0p, sbuf, gbuf);
    {   // ta: (4096x128)@(128x8192)
        dim3 grid(32, 64, 1);
        k_mma<0><<<grid, 256, SMEM_MMA_BYTES>>>(hp0, nullptr, nullptr, 128, TA, 8192,
                                                tab, 8192, 128, 0);
    }
    {   // tb: (4096x64)@(64x16384)
        dim3 grid(32, 128, 1);
        k_mma<0><<<grid, 256, SMEM_MMA_BYTES>>>(up0, nullptr, nullptr, 64, TB, 16384,
                                                tbb, 16384, 64, 0);
    }
    k_z1v<<<NN, 128>>>(tab, tbb, hp1, up1, gbuf, vmat);
    k_y0<<<NN / 4, 128>>>(sbuf, nfh, spb, Wp0, bp0, Wsc0, y0b);
    k_y1<<<NN / 2, 128>>>(vmat, nfh, spb, Wp1, Wsc1, y1b);
    k_stats<<<NG, 256>>>(y0b, y1b, batch, mean0, rs0, rs1);
    k_out<<<NN / 2, 128>>>(nfh, batch, y0b, y1b, mean0, rs0, rs1,
                           Ws0, bs0, Ws1, lnw0, lnb0, lnw1, out);
}

// round 17
// speedup vs baseline: 1.7059x; 1.0235x over previous
#include <cuda_runtime.h>
#include <cuda_fp16.h>
#include <stdint.h>
#include <math.h>

#define NN   4096
#define NG   64
#define NSP  10
#define EPSF 1e-5f
#define INV_H  0.08838834764831845f
#define INV_U  0.125f
#define INV_TP 0.0078125f
#define INV_SC 0.02795084971874737f
#define ISQRT3 0.57735026918962576f

// ---- static scratch ----
static __device__ float g_hp0[NN * 128];
static __device__ float g_hp1[NN * 384];
static __device__ float g_up0[NN * 64];
static __device__ float g_up1[NN * 192];
static __device__ unsigned short g_Axh[(size_t)NN * 16384];  // A fp16 hi plane
static __device__ unsigned short g_Axl[(size_t)NN * 16384];  // A fp16 lo plane
static __device__ unsigned short g_B0[16384 * 256];
static __device__ unsigned short g_TA[128 * 8192];
static __device__ unsigned short g_TB[64 * 16384];
static __device__ float g_z0p[(size_t)4 * NN * 256];
static __device__ float g_s[NN * 128];
static __device__ float g_g[NN * 128];
static __device__ unsigned short g_ta[(size_t)NN * 8192];    // fp16
static __device__ unsigned short g_tb[(size_t)NN * 16384];   // fp16
static __device__ float g_vmat[NN * 384];
static __device__ float g_y0[NN * 128];
static __device__ float g_y1[NN * 384];
static __device__ int   g_spi[NN];
static __device__ float g_mean0[NG], g_rs0[NG], g_rs1[NG];

// ---- prep: round B matrices to fp16 ----
__global__ void k_prep(const float* __restrict__ Wt00, const float* __restrict__ Wt11,
                       const float* __restrict__ Wt01, const float* __restrict__ Wt10)
{
    const int S0 = 16384 * 256, S1 = S0 + 128 * 8192, S2 = S1 + 64 * 16384;
    int idx = blockIdx.x * blockDim.x + threadIdx.x;
    if (idx < S0) {
        int k = idx >> 8;
        float w = (k < 8192) ? Wt00[idx] : Wt11[idx - 2097152] * ISQRT3;
        g_B0[idx] = __half_as_ushort(__float2half_rn(w));
    } else if (idx < S1) {
        int j = idx - S0;
        g_TA[j] = __half_as_ushort(__float2half_rn(Wt01[j]));
    } else if (idx < S2) {
        int j = idx - S1;
        int v = j >> 14, u = (j >> 7) & 127, w = j & 127;
        g_TB[j] = __half_as_ushort(__float2half_rn(Wt10[(u * 64 + v) * 128 + w]));
    }
}

__global__ void k_sp(const float* __restrict__ onehot, int* __restrict__ sp)
{
    int n = blockIdx.x * blockDim.x + threadIdx.x;
    if (n >= NN) return;
    const float* r = onehot + (size_t)n * NSP;
    int best = 0; float bv = r[0];
#pragma unroll
    for (int i = 1; i < NSP; i++) if (r[i] > bv) { bv = r[i]; best = i; }
    sp[n] = best;
}

// ---- projections ----
__global__ void k_proj_h(const float* __restrict__ nfh,
                         const float* __restrict__ Wh0, const float* __restrict__ Wh1,
                         float* __restrict__ hp0, float* __restrict__ hp1)
{
    int nb = blockIdx.x * 4, v = threadIdx.x;
    __shared__ float h0s[4][128], h1s[4][384];
    for (int i = v; i < 2048; i += 128) {
        int p = i >> 9, c = i & 511;
        float val = nfh[(size_t)(nb + p) * 512 + c];
        if (c < 128) h0s[p][c] = val; else h1s[p][c - 128] = val;
    }
    __syncthreads();
    float a0[4] = {}, a1[4][3] = {};
    for (int u = 0; u < 128; u++) {
        float w0 = Wh0[u * 128 + v], w1 = Wh1[u * 128 + v];
#pragma unroll
        for (int p = 0; p < 4; p++) {
            a0[p] += h0s[p][u] * w0;
            a1[p][0] += h1s[p][u * 3 + 0] * w1;
            a1[p][1] += h1s[p][u * 3 + 1] * w1;
            a1[p][2] += h1s[p][u * 3 + 2] * w1;
        }
    }
#pragma unroll
    for (int p = 0; p < 4; p++) {
        hp0[(size_t)(nb + p) * 128 + v] = a0[p] * INV_H;
#pragma unroll
        for (int i = 0; i < 3; i++)
            hp1[(size_t)(nb + p) * 384 + v * 3 + i] = a1[p][i] * INV_H;
    }
}

__global__ void k_proj_u(const float* __restrict__ nfu,
                         const float* __restrict__ Wu0, const float* __restrict__ Wu1,
                         float* __restrict__ up0, float* __restrict__ up1)
{
    int nb = blockIdx.x * 4, v = threadIdx.x;
    __shared__ float u0s[4][64], u1s[4][192];
    for (int i = v; i < 1024; i += 64) {
        int p = i >> 8, c = i & 255;
        float val = nfu[(size_t)(nb + p) * 256 + c];
        if (c < 64) u0s[p][c] = val; else u1s[p][c - 64] = val;
    }
    __syncthreads();
    float a0[4] = {}, a1[4][3] = {};
    for (int u = 0; u < 64; u++) {
        float w0 = Wu0[u * 64 + v], w1 = Wu1[u * 64 + v];
#pragma unroll
        for (int p = 0; p < 4; p++) {
            a0[p] += u0s[p][u] * w0;
            a1[p][0] += u1s[p][u * 3 + 0] * w1;
            a1[p][1] += u1s[p][u * 3 + 1] * w1;
            a1[p][2] += u1s[p][u * 3 + 2] * w1;
        }
    }
#pragma unroll
    for (int p = 0; p < 4; p++) {
        up0[(size_t)(nb + p) * 64 + v] = a0[p] * INV_U;
#pragma unroll
        for (int i = 0; i < 3; i++)
            up1[(size_t)(nb + p) * 192 + v * 3 + i] = a1[p][i] * INV_U;
    }
}

// ---- outer products -> A (pre-split fp16 hi/lo planes) ----
__global__ void k_xy(const float* __restrict__ hp0, const float* __restrict__ up0,
                     const float* __restrict__ hp1, const float* __restrict__ up1,
                     unsigned short* __restrict__ Axh, unsigned short* __restrict__ Axl)
{
    int n = blockIdx.x, tid = threadIdx.x;
    __shared__ float h0s[128], u0s[64], h1s[384], u1s[192];
    if (tid < 128) h0s[tid] = hp0[(size_t)n * 128 + tid];
    else if (tid < 192) u0s[tid - 128] = up0[(size_t)n * 64 + tid - 128];
    for (int i = tid; i < 384; i += 256) h1s[i] = hp1[(size_t)n * 384 + i];
    if (tid < 192) u1s[tid] = up1[(size_t)n * 192 + tid];
    __syncthreads();
    unsigned* Hh = (unsigned*)(Axh + (size_t)n * 16384);
    unsigned* Hl = (unsigned*)(Axl + (size_t)n * 16384);
    for (int c2 = tid; c2 < 4096; c2 += 256) {
        int c = c2 * 2;
        int u = c >> 6, v = c & 63;
        float a0 = h0s[u] * u0s[v];
        float a1 = h0s[u] * u0s[v + 1];
        __half2 h = __floats2half2_rn(a0, a1);
        float2 f = __half22float2(h);
        __half2 l = __floats2half2_rn(a0 - f.x, a1 - f.y);
        Hh[c2] = *(unsigned*)&h;
        Hl[c2] = *(unsigned*)&l;
        float b0 = h1s[u * 3] * u1s[v * 3] + h1s[u * 3 + 1] * u1s[v * 3 + 1]
                 + h1s[u * 3 + 2] * u1s[v * 3 + 2];
        float b1 = h1s[u * 3] * u1s[(v + 1) * 3] + h1s[u * 3 + 1] * u1s[(v + 1) * 3 + 1]
                 + h1s[u * 3 + 2] * u1s[(v + 1) * 3 + 2];
        __half2 hb = __floats2half2_rn(b0, b1);
        float2 fb = __half22float2(hb);
        __half2 lb = __floats2half2_rn(b0 - fb.x, b1 - fb.y);
        Hh[c2 + 4096] = *(unsigned*)&hb;
        Hl[c2 + 4096] = *(unsigned*)&lb;
    }
}

// ---- pipelined fp16 2-term split HMMA GEMM, 128x128x32 tiles, double-buffered ----
#define LDSM4(R, addr) asm volatile( \
    "ldmatrix.sync.aligned.m8n8.x4.shared.b16 {%0,%1,%2,%3}, [%4];" \
    : "=r"((R)[0]), "=r"((R)[1]), "=r"((R)[2]), "=r"((R)[3]) : "r"(addr))
#define LDSM4T(R0,R1,R2,R3, addr) asm volatile( \
    "ldmatrix.sync.aligned.m8n8.x4.trans.shared.b16 {%0,%1,%2,%3}, [%4];" \
    : "=r"(R0), "=r"(R1), "=r"(R2), "=r"(R3) : "r"(addr))
#define MMAH(Cv, Av, Bv) asm volatile( \
    "mma.sync.aligned.m16n8k16.row.col.f32.f16.f16.f32 " \
    "{%0,%1,%2,%3},{%4,%5,%6,%7},{%8,%9},{%0,%1,%2,%3};" \
    : "+f"((Cv)[0]), "+f"((Cv)[1]), "+f"((Cv)[2]), "+f"((Cv)[3]) \
    : "r"((Av)[0]), "r"((Av)[1]), "r"((Av)[2]), "r"((Av)[3]), "r"((Bv)[0]), "r"((Bv)[1]))
#define CPA16(dst, src) asm volatile( \
    "cp.async.cg.shared.global [%0], [%1], 16;" :: "r"(dst), "l"(src))

__device__ __forceinline__ void mma_tile(unsigned aHi, unsigned aLo,
                                         unsigned bA, float c[4][4][4])
{
#pragma unroll
    for (int kf = 0; kf < 2; kf++) {
        unsigned Af[4][4], Bf[4][2];
#pragma unroll
        for (int nq = 0; nq < 2; nq++) {
            unsigned r0, r1, r2, r3;
            LDSM4T(r0, r1, r2, r3, bA + kf * 4352 + nq * 32);
            Bf[2 * nq][0] = r0; Bf[2 * nq][1] = r1;
            Bf[2 * nq + 1][0] = r2; Bf[2 * nq + 1][1] = r3;
        }
#pragma unroll
        for (int mf = 0; mf < 4; mf++) LDSM4(Af[mf], aHi + mf * 1280 + kf * 32);
#pragma unroll
        for (int mf = 0; mf < 4; mf++)
#pragma unroll
            for (int nf = 0; nf < 4; nf++) MMAH(c[mf][nf], Af[mf], Bf[nf]);
#pragma unroll
        for (int mf = 0; mf < 4; mf++) LDSM4(Af[mf], aLo + mf * 1280 + kf * 32);
#pragma unroll
        for (int mf = 0; mf < 4; mf++)
#pragma unroll
            for (int nf = 0; nf < 4; nf++) MMAH(c[mf][nf], Af[mf], Bf[nf]);
    }
}

// smem halfs: sAh[2][5120] | sAl[2][5120] | sB[2][4352]
#define SMEM_MMA_BYTES ((2 * 5120 + 2 * 5120 + 2 * 4352) * 2)

// PRESPLIT=1: A given as fp16 hi/lo planes, loaded via cp.async (z0 path).
// PRESPLIT=0: fp32 A, split on the fly (ta/tb path).
// HALFOUT=1: C stored fp16.
template <int PRESPLIT, int HALFOUT>
__global__ __launch_bounds__(256, 2)
void k_mma(const float* __restrict__ A,
           const unsigned short* __restrict__ Aph, const unsigned short* __restrict__ Apl,
           int lda,
           const unsigned short* __restrict__ B, int ldb,
           void* __restrict__ Cv, int ldc, int Ktot, size_t partStride)
{
    extern __shared__ __align__(16) unsigned short sm[];
    unsigned short* sAh = sm;            // 2 x 5120
    unsigned short* sAl = sm + 10240;    // 2 x 5120
    unsigned short* sB  = sm + 20480;    // 2 x 4352
    const int kLen = Ktot / gridDim.z;
    const int kOff = blockIdx.z * kLen;
    const int nt = kLen >> 5;
    const int m0 = blockIdx.x * 128, c0 = blockIdx.y * 128;
    const int tid = threadIdx.x, lane = tid & 31, wid = tid >> 5;
    const int wm = wid & 1, wn = wid >> 1;
    const int ar = tid >> 1, ac = (tid & 1) << 4;

    const unsigned aHiB = (unsigned)__cvta_generic_to_shared(sAh);
    const unsigned aLoB = (unsigned)__cvta_generic_to_shared(sAl);
    const unsigned bB   = (unsigned)__cvta_generic_to_shared(sB);
    const unsigned aOff = (unsigned)(((wm * 64 + (lane & 15)) * 40 + (lane >> 4) * 8) * 2);
    const unsigned bOff = (unsigned)(((lane & 15) * 136 + wn * 32 + (lane >> 4) * 8) * 2);
    const int bi0r = tid >> 4, bi0c = (tid & 15) << 3;
    const int bi1r = (tid + 256) >> 4, bi1c = ((tid + 256) & 15) << 3;
    const int a0r = tid >> 2, a0s = (tid & 3) << 3;
    const int a1r = (tid + 256) >> 2, a1s = ((tid + 256) & 3) << 3;

    float c[4][4][4];
#pragma unroll
    for (int a = 0; a < 4; a++)
#pragma unroll
        for (int b = 0; b < 4; b++)
#pragma unroll
            for (int d = 0; d < 4; d++) c[a][b][d] = 0.f;

    float4 av[4];

#define LOADA(k0) do { \
    const float* ap_ = &A[(size_t)(m0 + ar) * lda + (k0) + ac]; \
    av[0] = *(const float4*)(ap_); \
    av[1] = *(const float4*)(ap_ + 4); \
    av[2] = *(const float4*)(ap_ + 8); \
    av[3] = *(const float4*)(ap_ + 12); \
} while (0)

#define STOREA(buf) do { \
    unsigned short* dh_ = sAh + (buf) * 5120 + ar * 40 + ac; \
    unsigned short* dl_ = sAl + (buf) * 5120 + ar * 40 + ac; \
    _Pragma("unroll") \
    for (int q_ = 0; q_ < 4; q_++) { \
        float4 v_ = av[q_]; \
        __half2 hA_ = __floats2half2_rn(v_.x, v_.y); \
        __half2 hB_ = __floats2half2_rn(v_.z, v_.w); \
        float2 fA_ = __half22float2(hA_), fB_ = __half22float2(hB_); \
        __half2 lA_ = __floats2half2_rn(v_.x - fA_.x, v_.y - fA_.y); \
        __half2 lB_ = __floats2half2_rn(v_.z - fB_.x, v_.w - fB_.y); \
        *(unsigned*)(dh_ + q_ * 4)     = *(unsigned*)&hA_; \
        *(unsigned*)(dh_ + q_ * 4 + 2) = *(unsigned*)&hB_; \
        *(unsigned*)(dl_ + q_ * 4)     = *(unsigned*)&lA_; \
        *(unsigned*)(dl_ + q_ * 4 + 2) = *(unsigned*)&lB_; \
    } \
} while (0)

#define LDAP(buf, k0) do { \
    unsigned dh0_ = aHiB + ((buf) * 5120 + a0r * 40 + a0s) * 2; \
    unsigned dh1_ = aHiB + ((buf) * 5120 + a1r * 40 + a1s) * 2; \
    unsigned dl0_ = aLoB + ((buf) * 5120 + a0r * 40 + a0s) * 2; \
    unsigned dl1_ = aLoB + ((buf) * 5120 + a1r * 40 + a1s) * 2; \
    CPA16(dh0_, &Aph[(size_t)(m0 + a0r) * lda + (k0) + a0s]); \
    CPA16(dh1_, &Aph[(size_t)(m0 + a1r) * lda + (k0) + a1s]); \
    CPA16(dl0_, &Apl[(size_t)(m0 + a0r) * lda + (k0) + a0s]); \
    CPA16(dl1_, &Apl[(size_t)(m0 + a1r) * lda + (k0) + a1s]); \
} while (0)

#define LDB(buf, k0) do { \
    unsigned d0_ = bB + ((buf) * 4352 + bi0r * 136 + bi0c) * 2; \
    CPA16(d0_, &B[(size_t)((k0) + bi0r) * ldb + c0 + bi0c]); \
    unsigned d1_ = bB + ((buf) * 4352 + bi1r * 136 + bi1c) * 2; \
    CPA16(d1_, &B[(size_t)((k0) + bi1r) * ldb + c0 + bi1c]); \
    asm volatile("cp.async.commit_group;"); \
} while (0)

    // prologue: tile 0
    if (PRESPLIT) {
        LDAP(0, kOff);
    } else {
        LOADA(kOff);
        STOREA(0);
    }
    LDB(0, kOff);
    asm volatile("cp.async.wait_group 0;");
    __syncthreads();

    for (int t = 0; t < nt; t++) {
        const int cur = t & 1, nxt = cur ^ 1;
        const bool more = (t + 1 < nt);
        if (more) {
            if (PRESPLIT) LDAP(nxt, kOff + (t + 1) * 32);
            LDB(nxt, kOff + (t + 1) * 32);
            if (!PRESPLIT) LOADA(kOff + (t + 1) * 32);
        }
        mma_tile(aHiB + cur * 10240 + aOff, aLoB + cur * 10240 + aOff,
                 bB + cur * 8704 + bOff, c);
        if (more) {
            if (!PRESPLIT) STOREA(nxt);
            asm volatile("cp.async.wait_group 0;");
        }
        __syncthreads();
    }

    int gq = lane >> 2, t4 = lane & 3;
    if (HALFOUT) {
        __half* C = (__half*)Cv;
#pragma unroll
        for (int mf = 0; mf < 4; mf++)
#pragma unroll
            for (int nf = 0; nf < 4; nf++) {
                int row = m0 + wm * 64 + mf * 16 + gq;
                int col = c0 + wn * 32 + nf * 8 + t4 * 2;
                *(__half2*)&C[(size_t)row * ldc + col] =
                    __floats2half2_rn(c[mf][nf][0], c[mf][nf][1]);
                *(__half2*)&C[(size_t)(row + 8) * ldc + col] =
                    __floats2half2_rn(c[mf][nf][2], c[mf][nf][3]);
            }
    } else {
        float* C = (float*)Cv + (size_t)blockIdx.z * partStride;
#pragma unroll
        for (int mf = 0; mf < 4; mf++)
#pragma unroll
            for (int nf = 0; nf < 4; nf++) {
                int row = m0 + wm * 64 + mf * 16 + gq;
                int col = c0 + wn * 32 + nf * 8 + t4 * 2;
                *(float2*)&C[(size_t)row * ldc + col] = make_float2(c[mf][nf][0], c[mf][nf][1]);
                *(float2*)&C[(size_t)(row + 8) * ldc + col] = make_float2(c[mf][nf][2], c[mf][nf][3]);
            }
    }
#undef LOADA
#undef STOREA
#undef LDAP
#undef LDB
}

// ---- z0 reduce + activations ----
__global__ void k_z0act(const float* __restrict__ P, float* __restrict__ s, float* __restrict__ g)
{
    int idx = blockIdx.x * blockDim.x + threadIdx.x;
    if (idx >= NN * 128) return;
    int n = idx >> 7, w = idx & 127;
    const size_t S = (size_t)NN * 256;
    size_t base = (size_t)n * 256;
    float za = (P[base + w] + P[S + base + w] + P[2 * S + base + w] + P[3 * S + base + w]) * INV_TP;
    float zb = (P[base + 128 + w] + P[S + base + 128 + w] + P[2 * S + base + 128 + w] + P[3 * S + base + 128 + w]) * INV_TP;
    s[idx] = za / (1.0f + __expf(-za));
    g[idx] = 1.0f / (1.0f + __expf(-zb));
}

// ---- z1 + gate (fp16 ta/tb) ----
__global__ void k_z1v(const unsigned short* __restrict__ ta, const unsigned short* __restrict__ tb,
                      const float* __restrict__ hp1, const float* __restrict__ up1,
                      const float* __restrict__ gg, float* __restrict__ vmat)
{
    int n = blockIdx.x, w = threadIdx.x;
    __shared__ float u1s[192], h1s[384];
    for (int i = w; i < 192; i += 128) u1s[i] = up1[(size_t)n * 192 + i];
    for (int i = w; i < 384; i += 128) h1s[i] = hp1[(size_t)n * 384 + i];
    __syncthreads();
    float a0 = 0.f, a1 = 0.f, a2 = 0.f;
    const __half* tap = (const __half*)ta + (size_t)n * 8192 + w;
    for (int v = 0; v < 64; v++) {
        float t = __half2float(tap[v * 128]);
        a0 += t * u1s[v * 3]; a1 += t * u1s[v * 3 + 1]; a2 += t * u1s[v * 3 + 2];
    }
    const __half* tbp = (const __half*)tb + (size_t)n * 16384 + w;
    for (int u = 0; u < 128; u++) {
        float t = __half2float(tbp[u * 128]);
        a0 += t * h1s[u * 3]; a1 += t * h1s[u * 3 + 1]; a2 += t * h1s[u * 3 + 2];
    }
    float gv = gg[(size_t)n * 128 + w];
    vmat[(size_t)n * 384 + w * 3 + 0] = a0 * INV_TP * gv;
    vmat[(size_t)n * 384 + w * 3 + 1] = a1 * INV_TP * gv;
    vmat[(size_t)n * 384 + w * 3 + 2] = a2 * INV_TP * gv;
}

// ---- y0 ----
__global__ void k_y0(const float* __restrict__ s, const float* __restrict__ nfh,
                     const int* __restrict__ sp, const float* __restrict__ Wp0,
                     const float* __restrict__ bp0, const float* __restrict__ Wsc0,
                     float* __restrict__ y0)
{
    int nb = blockIdx.x * 4, w = threadIdx.x;
    __shared__ float ss[4][128], h0s[4][128];
    __shared__ int sps[4];
    for (int i = w; i < 512; i += 128) {
        int p = i >> 7, c = i & 127;
        ss[p][c] = s[(size_t)(nb + p) * 128 + c];
        h0s[p][c] = nfh[(size_t)(nb + p) * 512 + c];
    }
    if (w < 4) sps[w] = sp[nb + w];
    __syncthreads();
    float a[4] = {}, b[4] = {};
    for (int u = 0; u < 128; u++) {
        float wp = Wp0[u * 128 + w];
#pragma unroll
        for (int p = 0; p < 4; p++) a[p] += ss[p][u] * wp;
#pragma unroll
        for (int p = 0; p < 4; p++) b[p] += h0s[p][u] * Wsc0[u * 1280 + sps[p] * 128 + w];
    }
    float bp = bp0[w];
#pragma unroll
    for (int p = 0; p < 4; p++)
        y0[(size_t)(nb + p) * 128 + w] = a[p] * INV_H + bp + b[p] * INV_SC;
}

// ---- y1 ----
__global__ void k_y1(const float* __restrict__ vmat, const float* __restrict__ nfh,
                     const int* __restrict__ sp, const float* __restrict__ Wp1,
                     const float* __restrict__ Wsc1, float* __restrict__ y1)
{
    int nb = blockIdx.x * 2, w = threadIdx.x;
    __shared__ float vs[2][384], h1s[2][384];
    __shared__ int sps[2];
    for (int i = w; i < 768; i += 128) {
        int p = i / 384, c = i % 384;
        vs[p][c] = vmat[(size_t)(nb + p) * 384 + c];
        h1s[p][c] = nfh[(size_t)(nb + p) * 512 + 128 + c];
    }
    if (w < 2) sps[w] = sp[nb + w];
    __syncthreads();
    float a[2][3] = {}, b[2][3] = {};
    for (int u = 0; u < 128; u++) {
        float wp = Wp1[u * 128 + w];
#pragma unroll
        for (int p = 0; p < 2; p++) {
            a[p][0] += vs[p][u * 3] * wp;
            a[p][1] += vs[p][u * 3 + 1] * wp;
            a[p][2] += vs[p][u * 3 + 2] * wp;
        }
#pragma unroll
        for (int p = 0; p < 2; p++) {
            float wsc = Wsc1[u * 1280 + sps[p] * 128 + w];
            b[p][0] += h1s[p][u * 3] * wsc;
            b[p][1] += h1s[p][u * 3 + 1] * wsc;
            b[p][2] += h1s[p][u * 3 + 2] * wsc;
        }
    }
#pragma unroll
    for (int p = 0; p < 2; p++)
#pragma unroll
        for (int i = 0; i < 3; i++)
            y1[(size_t)(nb + p) * 384 + w * 3 + i] = a[p][i] * INV_H + b[p][i] * INV_SC;
}

// ---- deterministic group stats ----
__device__ __forceinline__ int lowerBound(const int* b, int n, int val)
{
    int lo = 0, hi = n;
    while (lo < hi) { int mid = (lo + hi) >> 1; if (b[mid] < val) lo = mid + 1; else hi = mid; }
    return lo;
}

__global__ void k_stats(const float* __restrict__ y0, const float* __restrict__ y1,
                        const int* __restrict__ batch,
                        float* __restrict__ mean0, float* __restrict__ rs0, float* __restrict__ rs1)
{
    int g = blockIdx.x, tid = threadIdx.x;
    int lo = lowerBound(batch, NN, g);
    int hi = lowerBound(batch, NN, g + 1);
    int cntI = hi - lo;
    float cnt = cntI < 1 ? 1.0f : (float)cntI;
    double s0 = 0.0, q0 = 0.0, q1 = 0.0;
    for (int j = tid; j < cntI * 128; j += 256) {
        float v = y0[(size_t)lo * 128 + j];
        s0 += v; q0 += (double)v * v;
    }
    for (int j = tid; j < cntI * 384; j += 256) {
        float v = y1[(size_t)lo * 384 + j];
        q1 += (double)v * v;
    }
    __shared__ double r0[256], r1[256], r2[256];
    r0[tid] = s0; r1[tid] = q0; r2[tid] = q1;
    __syncthreads();
    for (int off = 128; off > 0; off >>= 1) {
        if (tid < off) { r0[tid] += r0[tid + off]; r1[tid] += r1[tid + off]; r2[tid] += r2[tid + off]; }
        __syncthreads();
    }
    if (tid == 0) {
        double m = r0[0] / ((double)cnt * 128.0);
        double v0 = r1[0] / ((double)cnt * 128.0) - m * m;
        if (v0 < 0.0) v0 = 0.0;
        double v1 = r2[0] / ((double)cnt * 384.0);
        mean0[g] = (float)m;
        rs0[g] = 1.0f / (sqrtf((float)v0) + EPSF);
        rs1[g] = 1.0f / (sqrtf((float)v1) + EPSF);
    }
}

// ---- final output ----
__global__ void k_out(const float* __restrict__ nfh, const int* __restrict__ batch,
                      const float* __restrict__ y0, const float* __restrict__ y1,
                      const float* __restrict__ mean0, const float* __restrict__ rs0,
                      const float* __restrict__ rs1,
                      const float* __restrict__ Ws0, const float* __restrict__ bs0,
                      const float* __restrict__ Ws1,
                      const float* __restrict__ lnw0, const float* __restrict__ lnb0,
                      const float* __restrict__ lnw1, float* __restrict__ out)
{
    int nb = blockIdx.x * 2, w = threadIdx.x;
    __shared__ float h0s[2][128], h1s[2][384];
    for (int i = w; i < 1024; i += 128) {
        int p = i >> 9, c = i & 511;
        float val = nfh[(size_t)(nb + p) * 512 + c];
        if (c < 128) h0s[p][c] = val; else h1s[p][c - 128] = val;
    }
    __syncthreads();
    float o0[2] = {}, o1[2][3] = {};
    for (int u = 0; u < 128; u++) {
        float w0 = Ws0[u * 128 + w], w1 = Ws1[u * 128 + w];
#pragma unroll
        for (int p = 0; p < 2; p++) {
            o0[p] += h0s[p][u] * w0;
            o1[p][0] += h1s[p][u * 3] * w1;
            o1[p][1] += h1s[p][u * 3 + 1] * w1;
            o1[p][2] += h1s[p][u * 3 + 2] * w1;
        }
    }
    float lw0 = lnw0[w], lb0 = lnb0[w], lw1 = lnw1[w], bsw = bs0[w];
#pragma unroll
    for (int p = 0; p < 2; p++) {
        int n = nb + p, b = batch[n];
        float m = mean0[b], r0v = rs0[b], r1v = rs1[b];
        out[(size_t)n * 512 + w] =
            (y0[(size_t)n * 128 + w] - m) * r0v * lw0 + lb0 + o0[p] * INV_H + bsw;
#pragma unroll
        for (int i = 0; i < 3; i++)
            out[(size_t)n * 512 + 128 + w * 3 + i] =
                y1[(size_t)n * 384 + w * 3 + i] * r1v * lw1 + o1[p][i] * INV_H;
    }
}

// ---- host launcher ----
static void* sym(const void* s) { void* p = nullptr; cudaGetSymbolAddress(&p, s); return p; }

extern "C" void kernel_launch(void* const* d_in, const int* in_sizes, int n_in,
                              void* d_out, int out_size)
{
    const float* nfh  = (const float*)d_in[0];
    const float* nfu  = (const float*)d_in[1];
    const float* oneh = (const float*)d_in[2];
    const int* batch  = (const int*)d_in[3];
    const float* Wh0  = (const float*)d_in[4];
    const float* Wh1  = (const float*)d_in[5];
    const float* Wu0  = (const float*)d_in[6];
    const float* Wu1  = (const float*)d_in[7];
    const float* Wt00 = (const float*)d_in[8];
    const float* Wt11 = (const float*)d_in[9];
    const float* Wt01 = (const float*)d_in[10];
    const float* Wt10 = (const float*)d_in[11];
    const float* Wp0  = (const float*)d_in[12];
    const float* bp0  = (const float*)d_in[13];
    const float* Wp1  = (const float*)d_in[14];
    const float* Wsc0 = (const float*)d_in[15];
    const float* Wsc1 = (const float*)d_in[16];
    const float* lnw0 = (const float*)d_in[17];
    const float* lnb0 = (const float*)d_in[18];
    const float* lnw1 = (const float*)d_in[19];
    const float* Ws0  = (const float*)d_in[20];
    const float* bs0  = (const float*)d_in[21];
    const float* Ws1  = (const float*)d_in[22];
    float* out = (float*)d_out;

    float* hp0  = (float*)sym(g_hp0);
    float* hp1  = (float*)sym(g_hp1);
    float* up0  = (float*)sym(g_up0);
    float* up1  = (float*)sym(g_up1);
    unsigned short* Axh = (unsigned short*)sym(g_Axh);
    unsigned short* Axl = (unsigned short*)sym(g_Axl);
    unsigned short* B0 = (unsigned short*)sym(g_B0);
    unsigned short* TA = (unsigned short*)sym(g_TA);
    unsigned short* TB = (unsigned short*)sym(g_TB);
    float* z0p  = (float*)sym(g_z0p);
    float* sbuf = (float*)sym(g_s);
    float* gbuf = (float*)sym(g_g);
    unsigned short* tab = (unsigned short*)sym(g_ta);
    unsigned short* tbb = (unsigned short*)sym(g_tb);
    float* vmat = (float*)sym(g_vmat);
    float* y0b  = (float*)sym(g_y0);
    float* y1b  = (float*)sym(g_y1);
    int*   spb  = (int*)sym(g_spi);
    float* mean0 = (float*)sym(g_mean0);
    float* rs0  = (float*)sym(g_rs0);
    float* rs1  = (float*)sym(g_rs1);

    cudaFuncSetAttribute(k_mma<0, 1>, cudaFuncAttributeMaxDynamicSharedMemorySize, SMEM_MMA_BYTES);
    cudaFuncSetAttribute(k_mma<1, 0>, cudaFuncAttributeMaxDynamicSharedMemorySize, SMEM_MMA_BYTES);

    k_prep<<<24576, 256>>>(Wt00, Wt11, Wt01, Wt10);
    k_sp<<<16, 256>>>(oneh, spb);
    k_proj_h<<<NN / 4, 128>>>(nfh, Wh0, Wh1, hp0, hp1);
    k_proj_u<<<NN / 4, 64>>>(nfu, Wu0, Wu1, up0, up1);
    k_xy<<<NN, 256>>>(hp0, up0, hp1, up1, Axh, Axl);
    {   // z0: (4096x16384)@(16384x256), split-K=4, pre-split A via cp.async
        dim3 grid(32, 2, 4);
        k_mma<1, 0><<<grid, 256, SMEM_MMA_BYTES>>>(nullptr, Axh, Axl, 16384, B0, 256,
                                                   z0p, 256, 16384, (size_t)NN * 256);
    }
    k_z0act<<<(NN * 128 + 255) / 256, 256>>>(z0p, sbuf, gbuf);
    {   // ta: (4096x128)@(128x8192), fp16 out
        dim3 grid(32, 64, 1);
        k_mma<0, 1><<<grid, 256, SMEM_MMA_BYTES>>>(hp0, nullptr, nullptr, 128, TA, 8192,
                                                   tab, 8192, 128, 0);
    }
    {   // tb: (4096x64)@(64x16384), fp16 out
        dim3 grid(32, 128, 1);
        k_mma<0, 1><<<grid, 256, SMEM_MMA_BYTES>>>(up0, nullptr, nullptr, 64, TB, 16384,
                                                   tbb, 16384, 64, 0);
    }
    k_z1v<<<NN, 128>>>(tab, tbb, hp1, up1, gbuf, vmat);
    k_y0<<<NN / 4, 128>>>(sbuf, nfh, spb, Wp0, bp0, Wsc0, y0b);
    k_y1<<<NN / 2, 128>>>(vmat, nfh, spb, Wp1, Wsc1, y1b);
    k_stats<<<NG, 256>>>(y0b, y1b, batch, mean0, rs0, rs1);
    k_out<<<NN / 2, 128>>>(nfh, batch, y0b, y1b, mean0, rs0, rs1,
                           Ws0, bs0, Ws1, lnw0, lnb0, lnw1, out);
}